// round 3
// baseline (speedup 1.0000x reference)
#include <cuda_runtime.h>
#include <math.h>

#define Bq    128
#define Mseq  1024
#define Ee    1024
#define Hh    8
#define Dd    128
#define MEMN  40
#define MFULL 1064
#define MIDN  64
#define ALPHA_C 1.3f
#define EPS_C   1e-5f
#define SQRT_D_C    11.313708498984760390f   /* sqrt(128) */
#define SQRT_MEM_C  6.3245553203367586640f   /* sqrt(40)  */

typedef unsigned long long u64;

/* ---------------- scratch (static device memory: allowed) ---------------- */
__device__ float g_q   [Bq * Ee];
__device__ float g_v1  [Bq * Ee];
__device__ float g_K   [(size_t)Bq * Mseq * Ee];   /* 512 MB */
__device__ float g_V2  [(size_t)Bq * Mseq * Ee];   /* 512 MB */
__device__ float g_pool[Bq * Hh * MIDN];
__device__ float g_logits[Bq * Hh * MFULL];

/* ---------------- packed f32x2 helpers (Blackwell FFMA2) ---------------- */
__device__ __forceinline__ u64 pk2(float x, float y) {
    u64 r; asm("mov.b64 %0, {%1, %2};" : "=l"(r) : "f"(x), "f"(y)); return r;
}
__device__ __forceinline__ u64 ff2(u64 a, u64 b, u64 c) {
    u64 d; asm("fma.rn.f32x2 %0, %1, %2, %3;" : "=l"(d) : "l"(a), "l"(b), "l"(c)); return d;
}
__device__ __forceinline__ float2 up2(u64 a) {
    float2 f; asm("mov.b64 {%0, %1}, %2;" : "=f"(f.x), "=f"(f.y) : "l"(a)); return f;
}

__device__ __forceinline__ void st_tile(float (*s)[132], int kl, int r, float4 v) {
    s[kl + 0][r] = v.x; s[kl + 1][r] = v.y; s[kl + 2][r] = v.z; s[kl + 3][r] = v.w;
}

/* =========================================================================
 * proj: C = groupnorm(celu(A @ W^T + bias)) , A:[N,1024] W:[1024,1024]
 * 128x128 tile per block, BK=16, 8x8 microtile, f32x2 packed FFMA.
 * Column tile == one groupnorm group (D=128), so the norm fuses in epilogue.
 * ========================================================================= */
__global__ void __launch_bounds__(256) proj_kernel(
    const float* __restrict__ A, const float* __restrict__ W,
    const float* __restrict__ bias, const float* __restrict__ gamma,
    const float* __restrict__ beta, float* __restrict__ C)
{
    __shared__ float As[2][16][132];
    __shared__ float Bs[2][16][132];

    const int tid = threadIdx.x;
    const int lr  = tid >> 2;      /* loader row 0..63  */
    const int lc  = tid & 3;       /* loader f4  0..3   */
    const int tx  = tid & 15, ty = tid >> 4;
    const int i0  = ty * 8, j0 = tx * 8;

    const size_t rowBase = (size_t)blockIdx.y * 128;
    const size_t colBase = (size_t)blockIdx.x * 128;
    const float4* A4 = (const float4*)(A + rowBase * 1024);
    const float4* W4 = (const float4*)(W + colBase * 1024);

    u64 acc[8][4];
#pragma unroll
    for (int i = 0; i < 8; i++)
#pragma unroll
        for (int j = 0; j < 4; j++) acc[i][j] = 0ULL;

    /* preload tile 0 */
    {
        float4 a0 = A4[lr * 256 + lc];
        float4 a1 = A4[(lr + 64) * 256 + lc];
        float4 b0 = W4[lr * 256 + lc];
        float4 b1 = W4[(lr + 64) * 256 + lc];
        int kl = lc * 4;
        st_tile(As[0], kl, lr,      a0);
        st_tile(As[0], kl, lr + 64, a1);
        st_tile(Bs[0], kl, lr,      b0);
        st_tile(Bs[0], kl, lr + 64, b1);
    }
    __syncthreads();

    for (int t = 0; t < 64; t++) {
        const int cur = t & 1, nxt = cur ^ 1;
        float4 pa0, pa1, pb0, pb1;
        if (t < 63) {
            int f4 = (t + 1) * 4 + lc;
            pa0 = A4[lr * 256 + f4];
            pa1 = A4[(lr + 64) * 256 + f4];
            pb0 = W4[lr * 256 + f4];
            pb1 = W4[(lr + 64) * 256 + f4];
        }
#pragma unroll
        for (int k = 0; k < 16; k++) {
            float4 av0 = *(const float4*)&As[cur][k][i0];
            float4 av1 = *(const float4*)&As[cur][k][i0 + 4];
            ulonglong2 bp0 = *(const ulonglong2*)&Bs[cur][k][j0];
            ulonglong2 bp1 = *(const ulonglong2*)&Bs[cur][k][j0 + 4];
            u64 bv[4] = {bp0.x, bp0.y, bp1.x, bp1.y};
            float av[8] = {av0.x, av0.y, av0.z, av0.w, av1.x, av1.y, av1.z, av1.w};
#pragma unroll
            for (int i = 0; i < 8; i++) {
                u64 ad = pk2(av[i], av[i]);
#pragma unroll
                for (int j = 0; j < 4; j++) acc[i][j] = ff2(ad, bv[j], acc[i][j]);
            }
        }
        if (t < 63) {
            int kl = lc * 4;
            st_tile(As[nxt], kl, lr,      pa0);
            st_tile(As[nxt], kl, lr + 64, pa1);
            st_tile(Bs[nxt], kl, lr,      pb0);
            st_tile(Bs[nxt], kl, lr + 64, pb1);
        }
        __syncthreads();
    }

    /* ------- epilogue: bias + celu + groupnorm (per row over 128 cols) --- */
    float v[8][8];
#pragma unroll
    for (int i = 0; i < 8; i++)
#pragma unroll
        for (int jp = 0; jp < 4; jp++) {
            float2 f = up2(acc[i][jp]);
            v[i][2 * jp] = f.x; v[i][2 * jp + 1] = f.y;
        }

    float bia[8], gam[8], bet[8];
#pragma unroll
    for (int j = 0; j < 8; j++) {
        size_t c = colBase + j0 + j;
        bia[j] = bias[c]; gam[j] = gamma[c]; bet[j] = beta[c];
    }
#pragma unroll
    for (int i = 0; i < 8; i++)
#pragma unroll
        for (int j = 0; j < 8; j++) {
            float x = v[i][j] + bia[j];
            v[i][j] = (x > 0.f) ? x : ALPHA_C * expm1f(x * (1.0f / ALPHA_C));
        }

    /* per-row partial sums; reuse As smem (4224 floats >= 4096) */
    float* rs = &As[0][0][0];
    float* rq = rs + 2048;
#pragma unroll
    for (int i = 0; i < 8; i++) {
        float s = 0.f, q = 0.f;
#pragma unroll
        for (int j = 0; j < 8; j++) { s += v[i][j]; q += v[i][j] * v[i][j]; }
        rs[(i0 + i) * 16 + tx] = s;
        rq[(i0 + i) * 16 + tx] = q;
    }
    __syncthreads();

#pragma unroll
    for (int i = 0; i < 8; i++) {
        int row = i0 + i;
        float S = 0.f, Q = 0.f;
#pragma unroll
        for (int p = 0; p < 16; p++) { S += rs[row * 16 + p]; Q += rq[row * 16 + p]; }
        float mean = S * (1.f / 128.f);
        float var  = Q * (1.f / 128.f) - mean * mean;
        float inv  = rsqrtf(var + EPS_C);
        float o[8];
#pragma unroll
        for (int j = 0; j < 8; j++) o[j] = (v[i][j] - mean) * inv * gam[j] + bet[j];
        float4* dst = (float4*)&C[(rowBase + row) * 1024 + colBase + j0];
        dst[0] = make_float4(o[0], o[1], o[2], o[3]);
        dst[1] = make_float4(o[4], o[5], o[6], o[7]);
    }
}

/* =========================================================================
 * attn_h: per (b,h) block. t[m,d] = q[b,h,d]*k[b,h,m,d]; h = relu(t@Wb^T+bb)
 * emits masked alpha logits (h . Wl + bl) and masked mean pool.
 * ========================================================================= */
__global__ void __launch_bounds__(256) attn_h_kernel(
    const float* __restrict__ mask, const float* __restrict__ mem,
    const float* __restrict__ Wb, const float* __restrict__ bb,
    const float* __restrict__ Wl, const float* __restrict__ bl)
{
    extern __shared__ float sm[];
    float* Wbt  = sm;                     /* [128][64]  transposed Wb */
    float* ts   = sm + 128 * 64;          /* [64][128]  q*k tile      */
    float* lred = ts + 64 * 128;          /* [64][16]                 */
    float* pr   = lred + 64 * 16;         /* [64][16]                 */
    float* msm  = pr + 64 * 16;           /* [1]                      */

    const int bh = blockIdx.x, b = bh >> 3, h = bh & 7;
    const int tid = threadIdx.x;

    /* transpose Wb (64x128 row-major) -> Wbt[d][o] */
    const float4* Wb4 = (const float4*)Wb;
    for (int idx = tid; idx < 2048; idx += 256) {
        int o = idx >> 5, dq = idx & 31;
        float4 w = Wb4[o * 32 + dq];
        Wbt[(dq * 4 + 0) * 64 + o] = w.x;
        Wbt[(dq * 4 + 1) * 64 + o] = w.y;
        Wbt[(dq * 4 + 2) * 64 + o] = w.z;
        Wbt[(dq * 4 + 3) * 64 + o] = w.w;
    }
    if (tid < 32) {
        float s = 0.f;
        for (int m = tid; m < MFULL; m += 32) {
            int mm = (m < Mseq) ? m : (m - Mseq);
            s += mask[b * Mseq + mm];
        }
#pragma unroll
        for (int o = 16; o; o >>= 1) s += __shfl_xor_sync(0xffffffffu, s, o);
        if (tid == 0) msm[0] = s;
    }

    /* loader role */
    const int mr = tid >> 5;
    const int dl = (tid & 31) * 4;
    const float4 qv = *(const float4*)&g_q[b * Ee + h * Dd + dl];

    /* compute role */
    const int o0 = (tid & 15) * 4;
    const int m0 = (tid >> 4) * 4;
    const float4 bbv = *(const float4*)&bb[o0];
    const float4 wlv = *(const float4*)&Wl[o0];
    const float bbf[4] = {bbv.x, bbv.y, bbv.z, bbv.w};
    const float wlf[4] = {wlv.x, wlv.y, wlv.z, wlv.w};
    const float bl0 = bl[0];
    float pools[4] = {0.f, 0.f, 0.f, 0.f};

    __syncthreads();   /* Wbt + msum ready */

    for (int p = 0; p < 17; p++) {
        const int mbase = p * 64;
        /* build t tile */
#pragma unroll
        for (int i = 0; i < 8; i++) {
            int ml = mr + i * 8;
            int mg = mbase + ml;
            float4 kv = make_float4(0.f, 0.f, 0.f, 0.f);
            if (mg < Mseq) {
                kv = *(const float4*)&g_K[((size_t)(b * Mseq + mg)) * Ee + h * Dd + dl];
            } else if (mg < MFULL) {
                float4 mv = *(const float4*)&mem[(size_t)(mg - Mseq) * Ee + h * Dd + dl];
                kv = make_float4(mv.x * SQRT_D_C, mv.y * SQRT_D_C,
                                 mv.z * SQRT_D_C, mv.w * SQRT_D_C);
            }
            *(float4*)&ts[ml * Dd + dl] =
                make_float4(kv.x * qv.x, kv.y * qv.y, kv.z * qv.z, kv.w * qv.w);
        }
        __syncthreads();

        float acc[4][4];
#pragma unroll
        for (int oi = 0; oi < 4; oi++)
#pragma unroll
            for (int mi = 0; mi < 4; mi++) acc[oi][mi] = 0.f;

#pragma unroll 4
        for (int d4 = 0; d4 < 128; d4 += 4) {
            float wf[16], tf[16];
            *(float4*)&wf[0]  = *(const float4*)&Wbt[(d4 + 0) * 64 + o0];
            *(float4*)&wf[4]  = *(const float4*)&Wbt[(d4 + 1) * 64 + o0];
            *(float4*)&wf[8]  = *(const float4*)&Wbt[(d4 + 2) * 64 + o0];
            *(float4*)&wf[12] = *(const float4*)&Wbt[(d4 + 3) * 64 + o0];
            *(float4*)&tf[0]  = *(const float4*)&ts[(m0 + 0) * 128 + d4];
            *(float4*)&tf[4]  = *(const float4*)&ts[(m0 + 1) * 128 + d4];
            *(float4*)&tf[8]  = *(const float4*)&ts[(m0 + 2) * 128 + d4];
            *(float4*)&tf[12] = *(const float4*)&ts[(m0 + 3) * 128 + d4];
#pragma unroll
            for (int j = 0; j < 4; j++)
#pragma unroll
                for (int oi = 0; oi < 4; oi++)
#pragma unroll
                    for (int mi = 0; mi < 4; mi++)
                        acc[oi][mi] += wf[j * 4 + oi] * tf[mi * 4 + j];
        }

        /* relu + logit partials + pool */
        float hr[4][4];
#pragma unroll
        for (int mi = 0; mi < 4; mi++) {
            float s = 0.f;
#pragma unroll
            for (int oi = 0; oi < 4; oi++) {
                float hv = fmaxf(acc[oi][mi] + bbf[oi], 0.f);
                hr[oi][mi] = hv;
                s += hv * wlf[oi];
            }
            lred[(m0 + mi) * 16 + (tid & 15)] = s;
        }
#pragma unroll
        for (int mi = 0; mi < 4; mi++) {
            int mg = mbase + m0 + mi;
            float mv = 0.f;
            if (mg < Mseq)       mv = mask[b * Mseq + mg];
            else if (mg < MFULL) mv = mask[b * Mseq + mg - Mseq];
#pragma unroll
            for (int oi = 0; oi < 4; oi++) pools[oi] += hr[oi][mi] * mv;
        }
        __syncthreads();

        if (tid < 64) {
            int mg = mbase + tid;
            if (mg < MFULL) {
                float s = bl0;
#pragma unroll
                for (int pp = 0; pp < 16; pp++) s += lred[tid * 16 + pp];
                float mv = (mg < Mseq) ? mask[b * Mseq + mg]
                                       : mask[b * Mseq + mg - Mseq];
                g_logits[bh * MFULL + mg] = (mv == 0.f) ? -1e9f : s;
            }
        }
        __syncthreads();
    }

    /* pool reduce */
#pragma unroll
    for (int oi = 0; oi < 4; oi++) pr[(o0 + oi) * 16 + (tid >> 4)] = pools[oi];
    __syncthreads();
    if (tid < 64) {
        float s = 0.f;
#pragma unroll
        for (int pp = 0; pp < 16; pp++) s += pr[tid * 16 + pp];
        g_pool[bh * 64 + tid] = s / msm[0];
    }
}

/* =========================================================================
 * finalize: softmax(logits), alpha_channel = sigmoid(pool@Wl2^T+bl2),
 * v2p = sum_m alpha * v2,  out = v1 * v2p * alpha_channel
 * ========================================================================= */
__global__ void __launch_bounds__(256) finalize_kernel(
    const float* __restrict__ mem, const float* __restrict__ Wl2,
    const float* __restrict__ bl2, float* __restrict__ out)
{
    __shared__ float alpha[MFULL];
    __shared__ float red[256];
    __shared__ float pool_s[64];
    __shared__ float vpart[256];

    const int bh = blockIdx.x, b = bh >> 3, h = bh & 7;
    const int tid = threadIdx.x;

    float mx = -INFINITY;
    for (int m = tid; m < MFULL; m += 256) {
        float l = g_logits[bh * MFULL + m];
        alpha[m] = l;
        mx = fmaxf(mx, l);
    }
    red[tid] = mx;
    __syncthreads();
    for (int s = 128; s > 0; s >>= 1) {
        if (tid < s) red[tid] = fmaxf(red[tid], red[tid + s]);
        __syncthreads();
    }
    mx = red[0];
    __syncthreads();

    float es = 0.f;
    for (int m = tid; m < MFULL; m += 256) {
        float e = expf(alpha[m] - mx);
        alpha[m] = e;
        es += e;
    }
    red[tid] = es;
    if (tid < 64) pool_s[tid] = g_pool[bh * 64 + tid];
    __syncthreads();
    for (int s = 128; s > 0; s >>= 1) {
        if (tid < s) red[tid] += red[tid + s];
        __syncthreads();
    }
    const float sumExp = red[0];

    const int d = tid & 127, half = tid >> 7;
    float acc = 0.f;
    for (int m = half; m < MFULL; m += 2) {
        float a = alpha[m];
        float v;
        if (m < Mseq) v = g_V2[((size_t)(b * Mseq + m)) * Ee + h * Dd + d];
        else          v = SQRT_MEM_C * mem[(size_t)(m - Mseq) * Ee + h * Dd + d];
        acc += a * v;
    }
    vpart[tid] = acc;
    __syncthreads();

    if (tid < 128) {
        float v2p = (vpart[tid] + vpart[tid + 128]) / sumExp;
        float s = bl2[d];
#pragma unroll
        for (int o = 0; o < 64; o++) s += pool_s[o] * Wl2[d * 64 + o];
        float ac = 1.f / (1.f + expf(-s));
        size_t oidx = (size_t)b * Ee + h * Dd + d;
        out[oidx] = g_v1[oidx] * v2p * ac;
    }
}

/* ========================================================================= */
extern "C" void kernel_launch(void* const* d_in, const int* in_sizes, int n_in,
                              void* d_out, int out_size)
{
    const float* query  = (const float*)d_in[0];
    const float* key    = (const float*)d_in[1];
    const float* mask   = (const float*)d_in[2];
    const float* value1 = (const float*)d_in[3];
    const float* value2 = (const float*)d_in[4];
    const float* Wq  = (const float*)d_in[5];  const float* bq  = (const float*)d_in[6];
    const float* gq  = (const float*)d_in[7];  const float* sq  = (const float*)d_in[8];
    const float* Wk  = (const float*)d_in[9];  const float* bk  = (const float*)d_in[10];
    const float* gk  = (const float*)d_in[11]; const float* sk  = (const float*)d_in[12];
    const float* Wv1 = (const float*)d_in[13]; const float* bv1 = (const float*)d_in[14];
    const float* gv1 = (const float*)d_in[15]; const float* sv1 = (const float*)d_in[16];
    const float* Wv2 = (const float*)d_in[17]; const float* bv2 = (const float*)d_in[18];
    const float* gv2 = (const float*)d_in[19]; const float* sv2 = (const float*)d_in[20];
    const float* mem = (const float*)d_in[21];
    const float* Wb  = (const float*)d_in[22]; const float* bb  = (const float*)d_in[23];
    const float* Wl  = (const float*)d_in[24]; const float* bl  = (const float*)d_in[25];
    const float* Wl2 = (const float*)d_in[26]; const float* bl2 = (const float*)d_in[27];
    float* out = (float*)d_out;

    void *pq, *pv1, *pK, *pV2;
    cudaGetSymbolAddress(&pq,  g_q);
    cudaGetSymbolAddress(&pv1, g_v1);
    cudaGetSymbolAddress(&pK,  g_K);
    cudaGetSymbolAddress(&pV2, g_V2);

    const int SMEM2 = (128 * 64 + 64 * 128 + 64 * 16 + 64 * 16 + 8) * 4;
    cudaFuncSetAttribute(attn_h_kernel,
                         cudaFuncAttributeMaxDynamicSharedMemorySize, SMEM2);

    /* small projections: q, v1 (128 rows each) */
    proj_kernel<<<dim3(8, 1), 256>>>(query,  Wq,  bq,  gq,  sq,  (float*)pq);
    proj_kernel<<<dim3(8, 1), 256>>>(value1, Wv1, bv1, gv1, sv1, (float*)pv1);
    /* big projections: k, v2 (131072 rows each) */
    proj_kernel<<<dim3(8, 1024), 256>>>(key,    Wk,  bk,  gk,  sk,  (float*)pK);
    proj_kernel<<<dim3(8, 1024), 256>>>(value2, Wv2, bv2, gv2, sv2, (float*)pV2);

    /* per-(b,h) low-rank scoring: logits + pool */
    attn_h_kernel<<<Bq * Hh, 256, SMEM2>>>(mask, mem, Wb, bb, Wl, bl);

    /* softmax + channel gate + weighted sum + output */
    finalize_kernel<<<Bq * Hh, 256>>>(mem, Wl2, bl2, out);
}

// round 5
// speedup vs baseline: 3.0127x; 3.0127x over previous
#include <cuda_runtime.h>
#include <math.h>
#include <stdint.h>

#define Bq    128
#define Mseq  1024
#define Ee    1024
#define Hh    8
#define Dd    128
#define MEMN  40
#define MFULL 1064
#define MIDN  64
#define ALPHA_C 1.3f
#define EPS_C   1e-5f
#define SQRT_D_C    11.313708498984760390f   /* sqrt(128) */
#define SQRT_MEM_C  6.3245553203367586640f   /* sqrt(40)  */

/* ---------------- scratch (static device memory: allowed) ---------------- */
__device__ float g_q   [Bq * Ee];
__device__ float g_v1  [Bq * Ee];
__device__ float g_K   [(size_t)Bq * Mseq * Ee];   /* 512 MB */
__device__ float g_V2  [(size_t)Bq * Mseq * Ee];   /* 512 MB */
__device__ float g_pool[Bq * Hh * MIDN];
__device__ float g_logits[Bq * Hh * MFULL];

/* ---------------- helpers ---------------- */
__device__ __forceinline__ uint32_t cvt_tf32(float x) {
    uint32_t r;
    asm("cvt.rna.tf32.f32 %0, %1;" : "=r"(r) : "f"(x));
    return r;
}

#define MMA_TF32(d, a, b)                                                   \
    asm volatile("mma.sync.aligned.m16n8k8.row.col.f32.tf32.tf32.f32 "      \
        "{%0,%1,%2,%3}, {%4,%5,%6,%7}, {%8,%9}, {%0,%1,%2,%3};"             \
        : "+f"((d)[0]), "+f"((d)[1]), "+f"((d)[2]), "+f"((d)[3])            \
        : "r"((a)[0]), "r"((a)[1]), "r"((a)[2]), "r"((a)[3]),               \
          "r"((b)[0]), "r"((b)[1]))

/* =========================================================================
 * proj_mma: C = groupnorm(celu(A @ W^T + bias))
 * A:[rows,1024], W:[1024,1024] row-major.  CTA tile 128x128, BK=16.
 * 8 warps in 2(M) x 4(N); warp computes 64x32 via m16n8k8 tf32 mma.sync.
 * Smem: row-major, stride 20 words (20 mod 32 => conflict-free frag LDS).
 * Groupnorm group (D=128) == CTA N-tile => fully fused epilogue.
 * grid = (8, rows/128), 256 threads.
 * ========================================================================= */
__global__ void __launch_bounds__(256, 2) proj_mma(
    const float* __restrict__ A, const float* __restrict__ W,
    const float* __restrict__ bias, const float* __restrict__ gamma,
    const float* __restrict__ beta, float* __restrict__ C)
{
    __shared__ uint32_t As[2][128][20];
    __shared__ uint32_t Ws[2][128][20];

    const int tid  = threadIdx.x;
    const int lane = tid & 31;
    const int wid  = tid >> 5;
    const int wm   = wid >> 2;          /* 0..1 : 64-row slab   */
    const int wn   = wid & 3;           /* 0..3 : 32-col slab   */
    const int g    = lane >> 2;         /* groupID 0..7         */
    const int tc   = lane & 3;          /* thread-in-group 0..3 */

    const size_t rowBase = (size_t)blockIdx.y * 128;
    const size_t colBase = (size_t)blockIdx.x * 128;

    /* loader role: thread t handles rows (t>>2) and (t>>2)+64, f4-col t&3 */
    const int wrow = tid >> 2;          /* 0..63 */
    const int wkq  = tid & 3;           /* 0..3  */
    const float4* A4r0 = (const float4*)(A + (rowBase + wrow)       * 1024);
    const float4* A4r1 = (const float4*)(A + (rowBase + wrow + 64)  * 1024);
    const float4* W4r0 = (const float4*)(W + (colBase + wrow)       * 1024);
    const float4* W4r1 = (const float4*)(W + (colBase + wrow + 64)  * 1024);

    float acc[4][4][4];
#pragma unroll
    for (int mt = 0; mt < 4; mt++)
#pragma unroll
        for (int nt = 0; nt < 4; nt++)
#pragma unroll
            for (int r = 0; r < 4; r++) acc[mt][nt][r] = 0.f;

    /* ---- preload chunk 0 ---- */
    {
        float4 a0 = A4r0[wkq], a1 = A4r1[wkq];
        float4 w0 = W4r0[wkq], w1 = W4r1[wkq];
        *(uint4*)&As[0][wrow][wkq * 4] =
            make_uint4(cvt_tf32(a0.x), cvt_tf32(a0.y), cvt_tf32(a0.z), cvt_tf32(a0.w));
        *(uint4*)&As[0][wrow + 64][wkq * 4] =
            make_uint4(cvt_tf32(a1.x), cvt_tf32(a1.y), cvt_tf32(a1.z), cvt_tf32(a1.w));
        *(uint4*)&Ws[0][wrow][wkq * 4] =
            make_uint4(cvt_tf32(w0.x), cvt_tf32(w0.y), cvt_tf32(w0.z), cvt_tf32(w0.w));
        *(uint4*)&Ws[0][wrow + 64][wkq * 4] =
            make_uint4(cvt_tf32(w1.x), cvt_tf32(w1.y), cvt_tf32(w1.z), cvt_tf32(w1.w));
    }
    __syncthreads();

    for (int c = 0; c < 64; c++) {
        const int buf = c & 1;
        float4 na0, na1, nw0, nw1;
        if (c < 63) {
            const int f4 = (c + 1) * 4 + wkq;
            na0 = A4r0[f4]; na1 = A4r1[f4];
            nw0 = W4r0[f4]; nw1 = W4r1[f4];
        }

#pragma unroll
        for (int ks = 0; ks < 2; ks++) {
            const int kk = ks * 8 + tc;
            uint32_t af[4][4], bf[4][2];
#pragma unroll
            for (int mt = 0; mt < 4; mt++) {
                const int r0 = wm * 64 + mt * 16 + g;
                af[mt][0] = As[buf][r0][kk];
                af[mt][1] = As[buf][r0 + 8][kk];
                af[mt][2] = As[buf][r0][kk + 4];
                af[mt][3] = As[buf][r0 + 8][kk + 4];
            }
#pragma unroll
            for (int nt = 0; nt < 4; nt++) {
                const int n0 = wn * 32 + nt * 8 + g;
                bf[nt][0] = Ws[buf][n0][kk];
                bf[nt][1] = Ws[buf][n0][kk + 4];
            }
#pragma unroll
            for (int mt = 0; mt < 4; mt++)
#pragma unroll
                for (int nt = 0; nt < 4; nt++)
                    MMA_TF32(acc[mt][nt], af[mt], bf[nt]);
        }

        if (c < 63) {
            __syncthreads();   /* everyone done reading buf^1 from iter c-1 */
            const int nb = buf ^ 1;
            *(uint4*)&As[nb][wrow][wkq * 4] =
                make_uint4(cvt_tf32(na0.x), cvt_tf32(na0.y), cvt_tf32(na0.z), cvt_tf32(na0.w));
            *(uint4*)&As[nb][wrow + 64][wkq * 4] =
                make_uint4(cvt_tf32(na1.x), cvt_tf32(na1.y), cvt_tf32(na1.z), cvt_tf32(na1.w));
            *(uint4*)&Ws[nb][wrow][wkq * 4] =
                make_uint4(cvt_tf32(nw0.x), cvt_tf32(nw0.y), cvt_tf32(nw0.z), cvt_tf32(nw0.w));
            *(uint4*)&Ws[nb][wrow + 64][wkq * 4] =
                make_uint4(cvt_tf32(nw1.x), cvt_tf32(nw1.y), cvt_tf32(nw1.z), cvt_tf32(nw1.w));
            __syncthreads();
        }
    }
    __syncthreads();

    /* ---------------- epilogue: bias + celu + groupnorm ------------------ */
    /* thread owns cols: colBase + wn*32 + nt*8 + 2tc (+1), rows per (mt,r) */
    float bia[4][2], gam[4][2], bet[4][2];
#pragma unroll
    for (int nt = 0; nt < 4; nt++) {
        const size_t col = colBase + wn * 32 + nt * 8 + 2 * tc;
        bia[nt][0] = bias[col];  bia[nt][1] = bias[col + 1];
        gam[nt][0] = gamma[col]; gam[nt][1] = gamma[col + 1];
        bet[nt][0] = beta[col];  bet[nt][1] = beta[col + 1];
    }

    float* rs = (float*)&As[0][0][0];      /* [128][4] row partial sums   */
    float* rq = rs + 512;                  /* [128][4] row partial sumsq  */

#pragma unroll
    for (int mt = 0; mt < 4; mt++)
#pragma unroll
        for (int r = 0; r < 2; r++) {
            float s = 0.f, q = 0.f;
#pragma unroll
            for (int nt = 0; nt < 4; nt++)
#pragma unroll
                for (int cc = 0; cc < 2; cc++) {
                    float x = acc[mt][nt][r * 2 + cc] + bia[nt][cc];
                    x = (x > 0.f) ? x : ALPHA_C * expm1f(x * (1.0f / ALPHA_C));
                    acc[mt][nt][r * 2 + cc] = x;
                    s += x; q += x * x;
                }
            s += __shfl_xor_sync(0xffffffffu, s, 1);
            s += __shfl_xor_sync(0xffffffffu, s, 2);
            q += __shfl_xor_sync(0xffffffffu, q, 1);
            q += __shfl_xor_sync(0xffffffffu, q, 2);
            if (tc == 0) {
                const int rl = wm * 64 + mt * 16 + r * 8 + g;
                rs[rl * 4 + wn] = s;
                rq[rl * 4 + wn] = q;
            }
        }
    __syncthreads();

#pragma unroll
    for (int mt = 0; mt < 4; mt++)
#pragma unroll
        for (int r = 0; r < 2; r++) {
            const int rl = wm * 64 + mt * 16 + r * 8 + g;
            float S = rs[rl * 4 + 0] + rs[rl * 4 + 1] + rs[rl * 4 + 2] + rs[rl * 4 + 3];
            float Q = rq[rl * 4 + 0] + rq[rl * 4 + 1] + rq[rl * 4 + 2] + rq[rl * 4 + 3];
            const float mean = S * (1.f / 128.f);
            const float var  = Q * (1.f / 128.f) - mean * mean;
            const float inv  = rsqrtf(var + EPS_C);
            float* Crow = C + (rowBase + rl) * 1024 + colBase + wn * 32 + 2 * tc;
#pragma unroll
            for (int nt = 0; nt < 4; nt++) {
                float2 o;
                o.x = (acc[mt][nt][r * 2 + 0] - mean) * inv * gam[nt][0] + bet[nt][0];
                o.y = (acc[mt][nt][r * 2 + 1] - mean) * inv * gam[nt][1] + bet[nt][1];
                *(float2*)&Crow[nt * 8] = o;
            }
        }
}

/* =========================================================================
 * attn_h: per (b,h) block. t[m,d] = q[b,h,d]*k[b,h,m,d]; h = relu(t@Wb^T+bb)
 * emits masked alpha logits (h . Wl + bl) and masked mean pool.
 * ========================================================================= */
__global__ void __launch_bounds__(256) attn_h_kernel(
    const float* __restrict__ mask, const float* __restrict__ mem,
    const float* __restrict__ Wb, const float* __restrict__ bb,
    const float* __restrict__ Wl, const float* __restrict__ bl)
{
    extern __shared__ float sm[];
    float* Wbt  = sm;                     /* [128][64]  transposed Wb */
    float* ts   = sm + 128 * 64;          /* [64][128]  q*k tile      */
    float* lred = ts + 64 * 128;          /* [64][16]                 */
    float* pr   = lred + 64 * 16;         /* [64][16]                 */
    float* msm  = pr + 64 * 16;           /* [1]                      */

    const int bh = blockIdx.x, b = bh >> 3, h = bh & 7;
    const int tid = threadIdx.x;

    const float4* Wb4 = (const float4*)Wb;
    for (int idx = tid; idx < 2048; idx += 256) {
        int o = idx >> 5, dq = idx & 31;
        float4 w = Wb4[o * 32 + dq];
        Wbt[(dq * 4 + 0) * 64 + o] = w.x;
        Wbt[(dq * 4 + 1) * 64 + o] = w.y;
        Wbt[(dq * 4 + 2) * 64 + o] = w.z;
        Wbt[(dq * 4 + 3) * 64 + o] = w.w;
    }
    if (tid < 32) {
        float s = 0.f;
        for (int m = tid; m < MFULL; m += 32) {
            int mm = (m < Mseq) ? m : (m - Mseq);
            s += mask[b * Mseq + mm];
        }
#pragma unroll
        for (int o = 16; o; o >>= 1) s += __shfl_xor_sync(0xffffffffu, s, o);
        if (tid == 0) msm[0] = s;
    }

    const int mr = tid >> 5;
    const int dl = (tid & 31) * 4;
    const float4 qv = *(const float4*)&g_q[b * Ee + h * Dd + dl];

    const int o0 = (tid & 15) * 4;
    const int m0 = (tid >> 4) * 4;
    const float4 bbv = *(const float4*)&bb[o0];
    const float4 wlv = *(const float4*)&Wl[o0];
    const float bbf[4] = {bbv.x, bbv.y, bbv.z, bbv.w};
    const float wlf[4] = {wlv.x, wlv.y, wlv.z, wlv.w};
    const float bl0 = bl[0];
    float pools[4] = {0.f, 0.f, 0.f, 0.f};

    __syncthreads();

    for (int p = 0; p < 17; p++) {
        const int mbase = p * 64;
#pragma unroll
        for (int i = 0; i < 8; i++) {
            int ml = mr + i * 8;
            int mg = mbase + ml;
            float4 kv = make_float4(0.f, 0.f, 0.f, 0.f);
            if (mg < Mseq) {
                kv = *(const float4*)&g_K[((size_t)(b * Mseq + mg)) * Ee + h * Dd + dl];
            } else if (mg < MFULL) {
                float4 mv = *(const float4*)&mem[(size_t)(mg - Mseq) * Ee + h * Dd + dl];
                kv = make_float4(mv.x * SQRT_D_C, mv.y * SQRT_D_C,
                                 mv.z * SQRT_D_C, mv.w * SQRT_D_C);
            }
            *(float4*)&ts[ml * Dd + dl] =
                make_float4(kv.x * qv.x, kv.y * qv.y, kv.z * qv.z, kv.w * qv.w);
        }
        __syncthreads();

        float acc[4][4];
#pragma unroll
        for (int oi = 0; oi < 4; oi++)
#pragma unroll
            for (int mi = 0; mi < 4; mi++) acc[oi][mi] = 0.f;

#pragma unroll 4
        for (int d4 = 0; d4 < 128; d4 += 4) {
            float wf[16], tf[16];
            *(float4*)&wf[0]  = *(const float4*)&Wbt[(d4 + 0) * 64 + o0];
            *(float4*)&wf[4]  = *(const float4*)&Wbt[(d4 + 1) * 64 + o0];
            *(float4*)&wf[8]  = *(const float4*)&Wbt[(d4 + 2) * 64 + o0];
            *(float4*)&wf[12] = *(const float4*)&Wbt[(d4 + 3) * 64 + o0];
            *(float4*)&tf[0]  = *(const float4*)&ts[(m0 + 0) * 128 + d4];
            *(float4*)&tf[4]  = *(const float4*)&ts[(m0 + 1) * 128 + d4];
            *(float4*)&tf[8]  = *(const float4*)&ts[(m0 + 2) * 128 + d4];
            *(float4*)&tf[12] = *(const float4*)&ts[(m0 + 3) * 128 + d4];
#pragma unroll
            for (int j = 0; j < 4; j++)
#pragma unroll
                for (int oi = 0; oi < 4; oi++)
#pragma unroll
                    for (int mi = 0; mi < 4; mi++)
                        acc[oi][mi] += wf[j * 4 + oi] * tf[mi * 4 + j];
        }

        float hr[4][4];
#pragma unroll
        for (int mi = 0; mi < 4; mi++) {
            float s = 0.f;
#pragma unroll
            for (int oi = 0; oi < 4; oi++) {
                float hv = fmaxf(acc[oi][mi] + bbf[oi], 0.f);
                hr[oi][mi] = hv;
                s += hv * wlf[oi];
            }
            lred[(m0 + mi) * 16 + (tid & 15)] = s;
        }
#pragma unroll
        for (int mi = 0; mi < 4; mi++) {
            int mg = mbase + m0 + mi;
            float mv = 0.f;
            if (mg < Mseq)       mv = mask[b * Mseq + mg];
            else if (mg < MFULL) mv = mask[b * Mseq + mg - Mseq];
#pragma unroll
            for (int oi = 0; oi < 4; oi++) pools[oi] += hr[oi][mi] * mv;
        }
        __syncthreads();

        if (tid < 64) {
            int mg = mbase + tid;
            if (mg < MFULL) {
                float s = bl0;
#pragma unroll
                for (int pp = 0; pp < 16; pp++) s += lred[tid * 16 + pp];
                float mv = (mg < Mseq) ? mask[b * Mseq + mg]
                                       : mask[b * Mseq + mg - Mseq];
                g_logits[bh * MFULL + mg] = (mv == 0.f) ? -1e9f : s;
            }
        }
        __syncthreads();
    }

#pragma unroll
    for (int oi = 0; oi < 4; oi++) pr[(o0 + oi) * 16 + (tid >> 4)] = pools[oi];
    __syncthreads();
    if (tid < 64) {
        float s = 0.f;
#pragma unroll
        for (int pp = 0; pp < 16; pp++) s += pr[tid * 16 + pp];
        g_pool[bh * 64 + tid] = s / msm[0];
    }
}

/* =========================================================================
 * finalize: softmax(logits), alpha_channel = sigmoid(pool@Wl2^T+bl2),
 * v2p = sum_m alpha * v2,  out = v1 * v2p * alpha_channel
 * ========================================================================= */
__global__ void __launch_bounds__(256) finalize_kernel(
    const float* __restrict__ mem, const float* __restrict__ Wl2,
    const float* __restrict__ bl2, float* __restrict__ out)
{
    __shared__ float alpha[MFULL];
    __shared__ float red[256];
    __shared__ float pool_s[64];
    __shared__ float vpart[256];

    const int bh = blockIdx.x, b = bh >> 3, h = bh & 7;
    const int tid = threadIdx.x;

    float mx = -INFINITY;
    for (int m = tid; m < MFULL; m += 256) {
        float l = g_logits[bh * MFULL + m];
        alpha[m] = l;
        mx = fmaxf(mx, l);
    }
    red[tid] = mx;
    __syncthreads();
    for (int s = 128; s > 0; s >>= 1) {
        if (tid < s) red[tid] = fmaxf(red[tid], red[tid + s]);
        __syncthreads();
    }
    mx = red[0];
    __syncthreads();

    float es = 0.f;
    for (int m = tid; m < MFULL; m += 256) {
        float e = expf(alpha[m] - mx);
        alpha[m] = e;
        es += e;
    }
    red[tid] = es;
    if (tid < 64) pool_s[tid] = g_pool[bh * 64 + tid];
    __syncthreads();
    for (int s = 128; s > 0; s >>= 1) {
        if (tid < s) red[tid] += red[tid + s];
        __syncthreads();
    }
    const float sumExp = red[0];

    const int d = tid & 127, half = tid >> 7;
    float acc = 0.f;
    for (int m = half; m < MFULL; m += 2) {
        float a = alpha[m];
        float v;
        if (m < Mseq) v = g_V2[((size_t)(b * Mseq + m)) * Ee + h * Dd + d];
        else          v = SQRT_MEM_C * mem[(size_t)(m - Mseq) * Ee + h * Dd + d];
        acc += a * v;
    }
    vpart[tid] = acc;
    __syncthreads();

    if (tid < 128) {
        float v2p = (vpart[tid] + vpart[tid + 128]) / sumExp;
        float s = bl2[d];
#pragma unroll
        for (int o = 0; o < 64; o++) s += pool_s[o] * Wl2[d * 64 + o];
        float ac = 1.f / (1.f + expf(-s));
        size_t oidx = (size_t)b * Ee + h * Dd + d;
        out[oidx] = g_v1[oidx] * v2p * ac;
    }
}

/* ========================================================================= */
extern "C" void kernel_launch(void* const* d_in, const int* in_sizes, int n_in,
                              void* d_out, int out_size)
{
    const float* query  = (const float*)d_in[0];
    const float* key    = (const float*)d_in[1];
    const float* mask   = (const float*)d_in[2];
    const float* value1 = (const float*)d_in[3];
    const float* value2 = (const float*)d_in[4];
    const float* Wq  = (const float*)d_in[5];  const float* bq  = (const float*)d_in[6];
    const float* gq  = (const float*)d_in[7];  const float* sq  = (const float*)d_in[8];
    const float* Wk  = (const float*)d_in[9];  const float* bk  = (const float*)d_in[10];
    const float* gk  = (const float*)d_in[11]; const float* sk  = (const float*)d_in[12];
    const float* Wv1 = (const float*)d_in[13]; const float* bv1 = (const float*)d_in[14];
    const float* gv1 = (const float*)d_in[15]; const float* sv1 = (const float*)d_in[16];
    const float* Wv2 = (const float*)d_in[17]; const float* bv2 = (const float*)d_in[18];
    const float* gv2 = (const float*)d_in[19]; const float* sv2 = (const float*)d_in[20];
    const float* mem = (const float*)d_in[21];
    const float* Wb  = (const float*)d_in[22]; const float* bb  = (const float*)d_in[23];
    const float* Wl  = (const float*)d_in[24]; const float* bl  = (const float*)d_in[25];
    const float* Wl2 = (const float*)d_in[26]; const float* bl2 = (const float*)d_in[27];
    float* out = (float*)d_out;

    void *pq, *pv1, *pK, *pV2;
    cudaGetSymbolAddress(&pq,  g_q);
    cudaGetSymbolAddress(&pv1, g_v1);
    cudaGetSymbolAddress(&pK,  g_K);
    cudaGetSymbolAddress(&pV2, g_V2);

    const int SMEM2 = (128 * 64 + 64 * 128 + 64 * 16 + 64 * 16 + 8) * 4;
    cudaFuncSetAttribute(attn_h_kernel,
                         cudaFuncAttributeMaxDynamicSharedMemorySize, SMEM2);

    /* projections on mma.sync tf32 tensor cores */
    proj_mma<<<dim3(8, 1),    256>>>(query,  Wq,  bq,  gq,  sq,  (float*)pq);
    proj_mma<<<dim3(8, 1),    256>>>(value1, Wv1, bv1, gv1, sv1, (float*)pv1);
    proj_mma<<<dim3(8, 1024), 256>>>(key,    Wk,  bk,  gk,  sk,  (float*)pK);
    proj_mma<<<dim3(8, 1024), 256>>>(value2, Wv2, bv2, gv2, sv2, (float*)pV2);

    /* per-(b,h) low-rank scoring: logits + pool */
    attn_h_kernel<<<Bq * Hh, 256, SMEM2>>>(mask, mem, Wb, bb, Wl, bl);

    /* softmax + channel gate + weighted sum + output */
    finalize_kernel<<<Bq * Hh, 256>>>(mem, Wl2, bl2, out);
}

// round 6
// speedup vs baseline: 4.3884x; 1.4567x over previous
#include <cuda_runtime.h>
#include <cuda_fp16.h>
#include <math.h>
#include <stdint.h>

#define Bq    128
#define Mseq  1024
#define Ee    1024
#define Hh    8
#define Dd    128
#define MEMN  40
#define MFULL 1064
#define MIDN  64
#define ALPHA_C 1.3f
#define EPS_C   1e-5f
#define SQRT_D_C    11.313708498984760390f   /* sqrt(128) */
#define SQRT_MEM_C  6.3245553203367586640f   /* sqrt(40)  */

/* ---------------- scratch (static device memory: allowed) ---------------- */
__device__ float g_q   [Bq * Ee];
__device__ float g_v1  [Bq * Ee];
__device__ float g_K   [(size_t)Bq * Mseq * Ee];   /* 512 MB */
__device__ float g_V2  [(size_t)Bq * Mseq * Ee];   /* 512 MB */
__device__ float g_pool[Bq * Hh * MIDN];
__device__ float g_logits[Bq * Hh * MFULL];

/* f16 copies of GEMM inputs */
__device__ __half g_hKey [(size_t)Bq * Mseq * Ee]; /* 256 MB */
__device__ __half g_hV2in[(size_t)Bq * Mseq * Ee]; /* 256 MB */
__device__ __half g_hQin [Bq * Ee];
__device__ __half g_hV1in[Bq * Ee];
__device__ __half g_hWq [Ee * Ee];
__device__ __half g_hWk [Ee * Ee];
__device__ __half g_hWv1[Ee * Ee];
__device__ __half g_hWv2[Ee * Ee];

/* ======================= helpers =========================== */
__device__ __forceinline__ uint32_t smem_u32(const void* p) {
    uint32_t a;
    asm("{ .reg .u64 t; cvta.to.shared.u64 t, %1; cvt.u32.u64 %0, t; }"
        : "=r"(a) : "l"(p));
    return a;
}
__device__ __forceinline__ void cp16(uint32_t s, const void* g) {
    asm volatile("cp.async.ca.shared.global [%0], [%1], 16;"
                 :: "r"(s), "l"(g) : "memory");
}
#define CP_COMMIT() asm volatile("cp.async.commit_group;" ::: "memory")
#define CP_WAIT(n)  asm volatile("cp.async.wait_group %0;" :: "n"(n) : "memory")

#define LDSM_X4(r, a)                                                        \
    asm volatile("ldmatrix.sync.aligned.m8n8.x4.shared.b16 {%0,%1,%2,%3}, [%4];" \
        : "=r"((r)[0]), "=r"((r)[1]), "=r"((r)[2]), "=r"((r)[3]) : "r"(a))
#define LDSM_X2(r, a)                                                        \
    asm volatile("ldmatrix.sync.aligned.m8n8.x2.shared.b16 {%0,%1}, [%2];"   \
        : "=r"((r)[0]), "=r"((r)[1]) : "r"(a))

#define MMA_F16(d, a, b)                                                     \
    asm volatile("mma.sync.aligned.m16n8k16.row.col.f32.f16.f16.f32 "        \
        "{%0,%1,%2,%3}, {%4,%5,%6,%7}, {%8,%9}, {%0,%1,%2,%3};"              \
        : "+f"((d)[0]), "+f"((d)[1]), "+f"((d)[2]), "+f"((d)[3])             \
        : "r"((a)[0]), "r"((a)[1]), "r"((a)[2]), "r"((a)[3]),                \
          "r"((b)[0]), "r"((b)[1]))

/* ---------------- f32 -> f16 conversion pre-pass ---------------- */
__global__ void __launch_bounds__(256) cvt_f16_kernel(
    const float4* __restrict__ in, uint4* __restrict__ out, int n8)
{
    for (int i = blockIdx.x * blockDim.x + threadIdx.x; i < n8;
         i += gridDim.x * blockDim.x) {
        float4 a = in[2 * i], b = in[2 * i + 1];
        __half2 h0 = __floats2half2_rn(a.x, a.y);
        __half2 h1 = __floats2half2_rn(a.z, a.w);
        __half2 h2 = __floats2half2_rn(b.x, b.y);
        __half2 h3 = __floats2half2_rn(b.z, b.w);
        out[i] = make_uint4(*(uint32_t*)&h0, *(uint32_t*)&h1,
                            *(uint32_t*)&h2, *(uint32_t*)&h3);
    }
}

/* =========================================================================
 * proj_h: C = groupnorm(celu(A @ W^T + bias)), fp16 mma.sync m16n8k16.
 * A:[rows,1024] f16, W:[1024,1024] f16 (both row-major; W rows = out cols).
 * CTA tile 128(M) x 256(N), BK=32, 8 warps (2x4) of 64x64 warp tiles.
 * cp.async 4-buffer pipeline (3 in flight) -> padded smem -> ldmatrix.
 * Smem row stride 40 halves (80B): conflict-free ldmatrix + 16B-aligned.
 * Groupnorm group (D=128) == half the CTA N-tile -> fused epilogue.
 * grid = (4, rows/128), 256 threads.
 * ========================================================================= */
#define RSTR    80                       /* row stride bytes (40 halves)   */
#define STAGE_B (384 * RSTR)             /* 128 A rows + 256 W rows        */
#define OFF_SB  (4 * STAGE_B)            /* bias  (256 f32)                */
#define OFF_SG  (OFF_SB + 1024)          /* gamma                          */
#define OFF_SE  (OFF_SG + 1024)          /* beta                           */
#define OFF_RS  (OFF_SE + 1024)          /* row sums  [128][4]             */
#define OFF_RQ  (OFF_RS + 2048)          /* row sumsq [128][4]             */
#define PROJ_SMEM (OFF_RQ + 2048)

__device__ __forceinline__ void proj_issue(
    uint32_t stage, const __half* __restrict__ hA,
    const __half* __restrict__ hW, size_t rowBase, size_t colBase,
    int ch, int tid)
{
#pragma unroll
    for (int i = 0; i < 2; i++) {
        int idx = tid + 256 * i;
        int r = idx >> 2, c = idx & 3;
        cp16(stage + r * RSTR + c * 16,
             hA + (rowBase + r) * 1024 + ch * 32 + c * 8);
    }
#pragma unroll
    for (int i = 0; i < 4; i++) {
        int idx = tid + 256 * i;
        int n = idx >> 2, c = idx & 3;
        cp16(stage + (128 + n) * RSTR + c * 16,
             hW + (colBase + n) * 1024 + ch * 32 + c * 8);
    }
}

__global__ void __launch_bounds__(256, 1) proj_h(
    const __half* __restrict__ hA, const __half* __restrict__ hW,
    const float* __restrict__ bias, const float* __restrict__ gamma,
    const float* __restrict__ beta, float* __restrict__ C)
{
    extern __shared__ char smem[];
    const uint32_t sb = smem_u32(smem);

    const int tid  = threadIdx.x;
    const int lane = tid & 31;
    const int wid  = tid >> 5;
    const int wm   = wid >> 2;          /* 0..1 : 64-row slab */
    const int wn   = wid & 3;           /* 0..3 : 64-col slab */
    const int g    = lane >> 2;
    const int tc   = lane & 3;

    const size_t rowBase = (size_t)blockIdx.y * 128;
    const size_t colBase = (size_t)blockIdx.x * 256;

    float acc[4][8][4];
#pragma unroll
    for (int mt = 0; mt < 4; mt++)
#pragma unroll
        for (int nt = 0; nt < 8; nt++)
#pragma unroll
            for (int z = 0; z < 4; z++) acc[mt][nt][z] = 0.f;

    /* prologue: 3 chunks in flight */
    for (int ch = 0; ch < 3; ch++) {
        proj_issue(sb + ch * STAGE_B, hA, hW, rowBase, colBase, ch, tid);
        CP_COMMIT();
    }

    /* precompute per-warp fragment smem addresses (stage-relative) */
    const uint32_t aAddrBase = (uint32_t)((wm * 64 + (lane & 15)) * RSTR + (lane >> 4) * 16);
    const uint32_t bAddrBase = (uint32_t)((128 + wn * 64 + (lane & 7)) * RSTR + ((lane >> 3) & 1) * 16);

    for (int ch = 0; ch < 32; ch++) {
        CP_WAIT(2);
        __syncthreads();
        if (ch + 3 < 32)
            proj_issue(sb + ((ch + 3) & 3) * STAGE_B, hA, hW, rowBase, colBase,
                       ch + 3, tid);
        CP_COMMIT();

        const uint32_t S = sb + (ch & 3) * STAGE_B;
#pragma unroll
        for (int ks = 0; ks < 2; ks++) {
            uint32_t af[4][4], bf[8][2];
#pragma unroll
            for (int mt = 0; mt < 4; mt++)
                LDSM_X4(af[mt], S + aAddrBase + mt * 16 * RSTR + ks * 32);
#pragma unroll
            for (int nt = 0; nt < 8; nt++)
                LDSM_X2(bf[nt], S + bAddrBase + nt * 8 * RSTR + ks * 32);
#pragma unroll
            for (int mt = 0; mt < 4; mt++)
#pragma unroll
                for (int nt = 0; nt < 8; nt++)
                    MMA_F16(acc[mt][nt], af[mt], bf[nt]);
        }
    }
    CP_WAIT(0);
    __syncthreads();

    /* ---------------- epilogue: bias + celu + groupnorm ------------------ */
    float* SB = (float*)(smem + OFF_SB);
    float* SG = (float*)(smem + OFF_SG);
    float* SE = (float*)(smem + OFF_SE);
    float* RS = (float*)(smem + OFF_RS);
    float* RQ = (float*)(smem + OFF_RQ);

    SB[tid] = bias [colBase + tid];
    SG[tid] = gamma[colBase + tid];
    SE[tid] = beta [colBase + tid];
    __syncthreads();

#pragma unroll
    for (int mt = 0; mt < 4; mt++)
#pragma unroll
        for (int half = 0; half < 2; half++) {
            const int r = wm * 64 + mt * 16 + half * 8 + g;
            float s = 0.f, q = 0.f;
#pragma unroll
            for (int nt = 0; nt < 8; nt++) {
                const int c0 = wn * 64 + nt * 8 + 2 * tc;
                float x0 = acc[mt][nt][half * 2 + 0] + SB[c0];
                float x1 = acc[mt][nt][half * 2 + 1] + SB[c0 + 1];
                x0 = (x0 > 0.f) ? x0 : ALPHA_C * expm1f(x0 * (1.0f / ALPHA_C));
                x1 = (x1 > 0.f) ? x1 : ALPHA_C * expm1f(x1 * (1.0f / ALPHA_C));
                acc[mt][nt][half * 2 + 0] = x0;
                acc[mt][nt][half * 2 + 1] = x1;
                s += x0 + x1; q += x0 * x0 + x1 * x1;
            }
            s += __shfl_xor_sync(0xffffffffu, s, 1);
            s += __shfl_xor_sync(0xffffffffu, s, 2);
            q += __shfl_xor_sync(0xffffffffu, q, 1);
            q += __shfl_xor_sync(0xffffffffu, q, 2);
            if (tc == 0) { RS[r * 4 + wn] = s; RQ[r * 4 + wn] = q; }
        }
    __syncthreads();

    const int gw = (wn >> 1) * 2;   /* first warp col-slab of my group */
#pragma unroll
    for (int mt = 0; mt < 4; mt++)
#pragma unroll
        for (int half = 0; half < 2; half++) {
            const int r = wm * 64 + mt * 16 + half * 8 + g;
            const float S = RS[r * 4 + gw] + RS[r * 4 + gw + 1];
            const float Q = RQ[r * 4 + gw] + RQ[r * 4 + gw + 1];
            const float mean = S * (1.f / 128.f);
            const float var  = Q * (1.f / 128.f) - mean * mean;
            const float inv  = rsqrtf(var + EPS_C);
            float* Crow = C + (rowBase + r) * 1024 + colBase;
#pragma unroll
            for (int nt = 0; nt < 8; nt++) {
                const int c0 = wn * 64 + nt * 8 + 2 * tc;
                float2 o;
                o.x = (acc[mt][nt][half * 2 + 0] - mean) * inv * SG[c0]     + SE[c0];
                o.y = (acc[mt][nt][half * 2 + 1] - mean) * inv * SG[c0 + 1] + SE[c0 + 1];
                *(float2*)&Crow[c0] = o;
            }
        }
}

/* =========================================================================
 * attn_h: per (b,h) block. t[m,d] = q[b,h,d]*k[b,h,m,d]; h = relu(t@Wb^T+bb)
 * emits masked alpha logits (h . Wl + bl) and masked mean pool.
 * ========================================================================= */
__global__ void __launch_bounds__(256) attn_h_kernel(
    const float* __restrict__ mask, const float* __restrict__ mem,
    const float* __restrict__ Wb, const float* __restrict__ bb,
    const float* __restrict__ Wl, const float* __restrict__ bl)
{
    extern __shared__ float sm[];
    float* Wbt  = sm;                     /* [128][64]  transposed Wb */
    float* ts   = sm + 128 * 64;          /* [64][128]  q*k tile      */
    float* lred = ts + 64 * 128;          /* [64][16]                 */
    float* pr   = lred + 64 * 16;         /* [64][16]                 */
    float* msm  = pr + 64 * 16;           /* [1]                      */

    const int bh = blockIdx.x, b = bh >> 3, h = bh & 7;
    const int tid = threadIdx.x;

    const float4* Wb4 = (const float4*)Wb;
    for (int idx = tid; idx < 2048; idx += 256) {
        int o = idx >> 5, dq = idx & 31;
        float4 w = Wb4[o * 32 + dq];
        Wbt[(dq * 4 + 0) * 64 + o] = w.x;
        Wbt[(dq * 4 + 1) * 64 + o] = w.y;
        Wbt[(dq * 4 + 2) * 64 + o] = w.z;
        Wbt[(dq * 4 + 3) * 64 + o] = w.w;
    }
    if (tid < 32) {
        float s = 0.f;
        for (int m = tid; m < MFULL; m += 32) {
            int mm = (m < Mseq) ? m : (m - Mseq);
            s += mask[b * Mseq + mm];
        }
#pragma unroll
        for (int o = 16; o; o >>= 1) s += __shfl_xor_sync(0xffffffffu, s, o);
        if (tid == 0) msm[0] = s;
    }

    const int mr = tid >> 5;
    const int dl = (tid & 31) * 4;
    const float4 qv = *(const float4*)&g_q[b * Ee + h * Dd + dl];

    const int o0 = (tid & 15) * 4;
    const int m0 = (tid >> 4) * 4;
    const float4 bbv = *(const float4*)&bb[o0];
    const float4 wlv = *(const float4*)&Wl[o0];
    const float bbf[4] = {bbv.x, bbv.y, bbv.z, bbv.w};
    const float wlf[4] = {wlv.x, wlv.y, wlv.z, wlv.w};
    const float bl0 = bl[0];
    float pools[4] = {0.f, 0.f, 0.f, 0.f};

    __syncthreads();

    for (int p = 0; p < 17; p++) {
        const int mbase = p * 64;
#pragma unroll
        for (int i = 0; i < 8; i++) {
            int ml = mr + i * 8;
            int mg = mbase + ml;
            float4 kv = make_float4(0.f, 0.f, 0.f, 0.f);
            if (mg < Mseq) {
                kv = *(const float4*)&g_K[((size_t)(b * Mseq + mg)) * Ee + h * Dd + dl];
            } else if (mg < MFULL) {
                float4 mv = *(const float4*)&mem[(size_t)(mg - Mseq) * Ee + h * Dd + dl];
                kv = make_float4(mv.x * SQRT_D_C, mv.y * SQRT_D_C,
                                 mv.z * SQRT_D_C, mv.w * SQRT_D_C);
            }
            *(float4*)&ts[ml * Dd + dl] =
                make_float4(kv.x * qv.x, kv.y * qv.y, kv.z * qv.z, kv.w * qv.w);
        }
        __syncthreads();

        float acc[4][4];
#pragma unroll
        for (int oi = 0; oi < 4; oi++)
#pragma unroll
            for (int mi = 0; mi < 4; mi++) acc[oi][mi] = 0.f;

#pragma unroll 4
        for (int d4 = 0; d4 < 128; d4 += 4) {
            float wf[16], tf[16];
            *(float4*)&wf[0]  = *(const float4*)&Wbt[(d4 + 0) * 64 + o0];
            *(float4*)&wf[4]  = *(const float4*)&Wbt[(d4 + 1) * 64 + o0];
            *(float4*)&wf[8]  = *(const float4*)&Wbt[(d4 + 2) * 64 + o0];
            *(float4*)&wf[12] = *(const float4*)&Wbt[(d4 + 3) * 64 + o0];
            *(float4*)&tf[0]  = *(const float4*)&ts[(m0 + 0) * 128 + d4];
            *(float4*)&tf[4]  = *(const float4*)&ts[(m0 + 1) * 128 + d4];
            *(float4*)&tf[8]  = *(const float4*)&ts[(m0 + 2) * 128 + d4];
            *(float4*)&tf[12] = *(const float4*)&ts[(m0 + 3) * 128 + d4];
#pragma unroll
            for (int j = 0; j < 4; j++)
#pragma unroll
                for (int oi = 0; oi < 4; oi++)
#pragma unroll
                    for (int mi = 0; mi < 4; mi++)
                        acc[oi][mi] += wf[j * 4 + oi] * tf[mi * 4 + j];
        }

        float hr[4][4];
#pragma unroll
        for (int mi = 0; mi < 4; mi++) {
            float s = 0.f;
#pragma unroll
            for (int oi = 0; oi < 4; oi++) {
                float hv = fmaxf(acc[oi][mi] + bbf[oi], 0.f);
                hr[oi][mi] = hv;
                s += hv * wlf[oi];
            }
            lred[(m0 + mi) * 16 + (tid & 15)] = s;
        }
#pragma unroll
        for (int mi = 0; mi < 4; mi++) {
            int mg = mbase + m0 + mi;
            float mv = 0.f;
            if (mg < Mseq)       mv = mask[b * Mseq + mg];
            else if (mg < MFULL) mv = mask[b * Mseq + mg - Mseq];
#pragma unroll
            for (int oi = 0; oi < 4; oi++) pools[oi] += hr[oi][mi] * mv;
        }
        __syncthreads();

        if (tid < 64) {
            int mg = mbase + tid;
            if (mg < MFULL) {
                float s = bl0;
#pragma unroll
                for (int pp = 0; pp < 16; pp++) s += lred[tid * 16 + pp];
                float mv = (mg < Mseq) ? mask[b * Mseq + mg]
                                       : mask[b * Mseq + mg - Mseq];
                g_logits[bh * MFULL + mg] = (mv == 0.f) ? -1e9f : s;
            }
        }
        __syncthreads();
    }

#pragma unroll
    for (int oi = 0; oi < 4; oi++) pr[(o0 + oi) * 16 + (tid >> 4)] = pools[oi];
    __syncthreads();
    if (tid < 64) {
        float s = 0.f;
#pragma unroll
        for (int pp = 0; pp < 16; pp++) s += pr[tid * 16 + pp];
        g_pool[bh * 64 + tid] = s / msm[0];
    }
}

/* =========================================================================
 * finalize: softmax(logits), alpha_channel = sigmoid(pool@Wl2^T+bl2),
 * v2p = sum_m alpha * v2,  out = v1 * v2p * alpha_channel
 * ========================================================================= */
__global__ void __launch_bounds__(256) finalize_kernel(
    const float* __restrict__ mem, const float* __restrict__ Wl2,
    const float* __restrict__ bl2, float* __restrict__ out)
{
    __shared__ float alpha[MFULL];
    __shared__ float red[256];
    __shared__ float pool_s[64];
    __shared__ float vpart[256];

    const int bh = blockIdx.x, b = bh >> 3, h = bh & 7;
    const int tid = threadIdx.x;

    float mx = -INFINITY;
    for (int m = tid; m < MFULL; m += 256) {
        float l = g_logits[bh * MFULL + m];
        alpha[m] = l;
        mx = fmaxf(mx, l);
    }
    red[tid] = mx;
    __syncthreads();
    for (int s = 128; s > 0; s >>= 1) {
        if (tid < s) red[tid] = fmaxf(red[tid], red[tid + s]);
        __syncthreads();
    }
    mx = red[0];
    __syncthreads();

    float es = 0.f;
    for (int m = tid; m < MFULL; m += 256) {
        float e = expf(alpha[m] - mx);
        alpha[m] = e;
        es += e;
    }
    red[tid] = es;
    if (tid < 64) pool_s[tid] = g_pool[bh * 64 + tid];
    __syncthreads();
    for (int s = 128; s > 0; s >>= 1) {
        if (tid < s) red[tid] += red[tid + s];
        __syncthreads();
    }
    const float sumExp = red[0];

    const int d = tid & 127, half = tid >> 7;
    float acc = 0.f;
    for (int m = half; m < MFULL; m += 2) {
        float a = alpha[m];
        float v;
        if (m < Mseq) v = g_V2[((size_t)(b * Mseq + m)) * Ee + h * Dd + d];
        else          v = SQRT_MEM_C * mem[(size_t)(m - Mseq) * Ee + h * Dd + d];
        acc += a * v;
    }
    vpart[tid] = acc;
    __syncthreads();

    if (tid < 128) {
        float v2p = (vpart[tid] + vpart[tid + 128]) / sumExp;
        float s = bl2[d];
#pragma unroll
        for (int o = 0; o < 64; o++) s += pool_s[o] * Wl2[d * 64 + o];
        float ac = 1.f / (1.f + expf(-s));
        size_t oidx = (size_t)b * Ee + h * Dd + d;
        out[oidx] = g_v1[oidx] * v2p * ac;
    }
}

/* ========================================================================= */
extern "C" void kernel_launch(void* const* d_in, const int* in_sizes, int n_in,
                              void* d_out, int out_size)
{
    const float* query  = (const float*)d_in[0];
    const float* key    = (const float*)d_in[1];
    const float* mask   = (const float*)d_in[2];
    const float* value1 = (const float*)d_in[3];
    const float* value2 = (const float*)d_in[4];
    const float* Wq  = (const float*)d_in[5];  const float* bq  = (const float*)d_in[6];
    const float* gq  = (const float*)d_in[7];  const float* sq  = (const float*)d_in[8];
    const float* Wk  = (const float*)d_in[9];  const float* bk  = (const float*)d_in[10];
    const float* gk  = (const float*)d_in[11]; const float* sk  = (const float*)d_in[12];
    const float* Wv1 = (const float*)d_in[13]; const float* bv1 = (const float*)d_in[14];
    const float* gv1 = (const float*)d_in[15]; const float* sv1 = (const float*)d_in[16];
    const float* Wv2 = (const float*)d_in[17]; const float* bv2 = (const float*)d_in[18];
    const float* gv2 = (const float*)d_in[19]; const float* sv2 = (const float*)d_in[20];
    const float* mem = (const float*)d_in[21];
    const float* Wb  = (const float*)d_in[22]; const float* bb  = (const float*)d_in[23];
    const float* Wl  = (const float*)d_in[24]; const float* bl  = (const float*)d_in[25];
    const float* Wl2 = (const float*)d_in[26]; const float* bl2 = (const float*)d_in[27];
    float* out = (float*)d_out;

    void *pq, *pv1, *pK, *pV2;
    cudaGetSymbolAddress(&pq,  g_q);
    cudaGetSymbolAddress(&pv1, g_v1);
    cudaGetSymbolAddress(&pK,  g_K);
    cudaGetSymbolAddress(&pV2, g_V2);
    void *phKey, *phV2, *phQ, *phV1, *phWq, *phWk, *phWv1, *phWv2;
    cudaGetSymbolAddress(&phKey, g_hKey);
    cudaGetSymbolAddress(&phV2,  g_hV2in);
    cudaGetSymbolAddress(&phQ,   g_hQin);
    cudaGetSymbolAddress(&phV1,  g_hV1in);
    cudaGetSymbolAddress(&phWq,  g_hWq);
    cudaGetSymbolAddress(&phWk,  g_hWk);
    cudaGetSymbolAddress(&phWv1, g_hWv1);
    cudaGetSymbolAddress(&phWv2, g_hWv2);

    cudaFuncSetAttribute(proj_h, cudaFuncAttributeMaxDynamicSharedMemorySize,
                         PROJ_SMEM);
    const int SMEM2 = (128 * 64 + 64 * 128 + 64 * 16 + 64 * 16 + 8) * 4;
    cudaFuncSetAttribute(attn_h_kernel,
                         cudaFuncAttributeMaxDynamicSharedMemorySize, SMEM2);

    /* f32 -> f16 pre-pass */
    const int BIGN8 = (int)(((size_t)Bq * Mseq * Ee) / 8);
    cvt_f16_kernel<<<4096, 256>>>((const float4*)key,    (uint4*)phKey, BIGN8);
    cvt_f16_kernel<<<4096, 256>>>((const float4*)value2, (uint4*)phV2,  BIGN8);
    cvt_f16_kernel<<<128,  256>>>((const float4*)query,  (uint4*)phQ,   Bq * Ee / 8);
    cvt_f16_kernel<<<128,  256>>>((const float4*)value1, (uint4*)phV1,  Bq * Ee / 8);
    cvt_f16_kernel<<<512,  256>>>((const float4*)Wq,  (uint4*)phWq,  Ee * Ee / 8);
    cvt_f16_kernel<<<512,  256>>>((const float4*)Wk,  (uint4*)phWk,  Ee * Ee / 8);
    cvt_f16_kernel<<<512,  256>>>((const float4*)Wv1, (uint4*)phWv1, Ee * Ee / 8);
    cvt_f16_kernel<<<512,  256>>>((const float4*)Wv2, (uint4*)phWv2, Ee * Ee / 8);

    /* projections on fp16 mma.sync tensor cores */
    proj_h<<<dim3(4, 1),    256, PROJ_SMEM>>>((const __half*)phQ,   (const __half*)phWq,
                                              bq,  gq,  sq,  (float*)pq);
    proj_h<<<dim3(4, 1),    256, PROJ_SMEM>>>((const __half*)phV1,  (const __half*)phWv1,
                                              bv1, gv1, sv1, (float*)pv1);
    proj_h<<<dim3(4, 1024), 256, PROJ_SMEM>>>((const __half*)phKey, (const __half*)phWk,
                                              bk,  gk,  sk,  (float*)pK);
    proj_h<<<dim3(4, 1024), 256, PROJ_SMEM>>>((const __half*)phV2,  (const __half*)phWv2,
                                              bv2, gv2, sv2, (float*)pV2);

    /* per-(b,h) low-rank scoring: logits + pool */
    attn_h_kernel<<<Bq * Hh, 256, SMEM2>>>(mask, mem, Wb, bb, Wl, bl);

    /* softmax + channel gate + weighted sum + output */
    finalize_kernel<<<Bq * Hh, 256>>>(mem, Wl2, bl2, out);
}

// round 7
// speedup vs baseline: 5.0701x; 1.1553x over previous
#include <cuda_runtime.h>
#include <cuda_fp16.h>
#include <math.h>
#include <stdint.h>

#define Bq    128
#define Mseq  1024
#define Ee    1024
#define Hh    8
#define Dd    128
#define MEMN  40
#define MFULL 1064
#define MIDN  64
#define ALPHA_C 1.3f
#define EPS_C   1e-5f
#define SQRT_D_C    11.313708498984760390f   /* sqrt(128) */
#define SQRT_MEM_C  6.3245553203367586640f   /* sqrt(40)  */

/* ---------------- scratch (static device memory: allowed) ---------------- */
__device__ float  g_q   [Bq * Ee];
__device__ float  g_v1  [Bq * Ee];
__device__ float  g_pool[Bq * Hh * MIDN];
__device__ float  g_logits[Bq * Hh * MFULL];

__device__ __half g_hKey [(size_t)Bq * Mseq * Ee]; /* f16 key input    */
__device__ __half g_hV2in[(size_t)Bq * Mseq * Ee]; /* f16 value2 input */
__device__ __half g_hKout[(size_t)Bq * Mseq * Ee]; /* projected K f16  */
__device__ __half g_hV2out[(size_t)Bq * Mseq * Ee];/* projected V2 f16 */
__device__ __half g_hQin [Bq * Ee];
__device__ __half g_hV1in[Bq * Ee];
__device__ __half g_hWq [Ee * Ee];
__device__ __half g_hWk [Ee * Ee];
__device__ __half g_hWv1[Ee * Ee];
__device__ __half g_hWv2[Ee * Ee];
__device__ __half g_hMemK[MEMN * Ee];              /* sqrt(D)  * mem   */
__device__ __half g_hMemV[MEMN * Ee];              /* sqrt(MEM)* mem   */

/* ======================= helpers =========================== */
__device__ __forceinline__ uint32_t smem_u32(const void* p) {
    uint32_t a;
    asm("{ .reg .u64 t; cvta.to.shared.u64 t, %1; cvt.u32.u64 %0, t; }"
        : "=r"(a) : "l"(p));
    return a;
}
__device__ __forceinline__ void cp16(uint32_t s, const void* g) {
    asm volatile("cp.async.ca.shared.global [%0], [%1], 16;"
                 :: "r"(s), "l"(g) : "memory");
}
#define CP_COMMIT() asm volatile("cp.async.commit_group;" ::: "memory")
#define CP_WAIT(n)  asm volatile("cp.async.wait_group %0;" :: "n"(n) : "memory")

#define LDSM_X4(r, a)                                                        \
    asm volatile("ldmatrix.sync.aligned.m8n8.x4.shared.b16 {%0,%1,%2,%3}, [%4];" \
        : "=r"((r)[0]), "=r"((r)[1]), "=r"((r)[2]), "=r"((r)[3]) : "r"(a))
#define LDSM_X2(r, a)                                                        \
    asm volatile("ldmatrix.sync.aligned.m8n8.x2.shared.b16 {%0,%1}, [%2];"   \
        : "=r"((r)[0]), "=r"((r)[1]) : "r"(a))

#define MMA_F16(d, a, b)                                                     \
    asm volatile("mma.sync.aligned.m16n8k16.row.col.f32.f16.f16.f32 "        \
        "{%0,%1,%2,%3}, {%4,%5,%6,%7}, {%8,%9}, {%0,%1,%2,%3};"              \
        : "+f"((d)[0]), "+f"((d)[1]), "+f"((d)[2]), "+f"((d)[3])             \
        : "r"((a)[0]), "r"((a)[1]), "r"((a)[2]), "r"((a)[3]),                \
          "r"((b)[0]), "r"((b)[1]))

/* ---------------- f32 -> f16 conversion pre-pass ---------------- */
__global__ void __launch_bounds__(256) cvt_f16_kernel(
    const float4* __restrict__ in, uint4* __restrict__ out, int n8)
{
    for (int i = blockIdx.x * blockDim.x + threadIdx.x; i < n8;
         i += gridDim.x * blockDim.x) {
        float4 a = in[2 * i], b = in[2 * i + 1];
        __half2 h0 = __floats2half2_rn(a.x, a.y);
        __half2 h1 = __floats2half2_rn(a.z, a.w);
        __half2 h2 = __floats2half2_rn(b.x, b.y);
        __half2 h3 = __floats2half2_rn(b.z, b.w);
        out[i] = make_uint4(*(uint32_t*)&h0, *(uint32_t*)&h1,
                            *(uint32_t*)&h2, *(uint32_t*)&h3);
    }
}
__global__ void __launch_bounds__(256) cvt_mem_kernel(
    const float* __restrict__ mem, __half* __restrict__ mk,
    __half* __restrict__ mv, int n)
{
    for (int i = blockIdx.x * blockDim.x + threadIdx.x; i < n;
         i += gridDim.x * blockDim.x) {
        float m = mem[i];
        mk[i] = __float2half(m * SQRT_D_C);
        mv[i] = __float2half(m * SQRT_MEM_C);
    }
}

/* =========================================================================
 * proj_h: C = groupnorm(celu(A @ W^T + bias)), fp16 mma.sync m16n8k16.
 * CTA tile 128(M) x 256(N), BK=32, 8 warps (2x4) of 64x64 warp tiles.
 * Output type templated: f32 (q, v1) or f16 (K, V2).
 * ========================================================================= */
#define RSTR    80
#define STAGE_B (384 * RSTR)
#define OFF_SB  (4 * STAGE_B)
#define OFF_SG  (OFF_SB + 1024)
#define OFF_SE  (OFF_SG + 1024)
#define OFF_RS  (OFF_SE + 1024)
#define OFF_RQ  (OFF_RS + 2048)
#define PROJ_SMEM (OFF_RQ + 2048)

__device__ __forceinline__ void proj_issue(
    uint32_t stage, const __half* __restrict__ hA,
    const __half* __restrict__ hW, size_t rowBase, size_t colBase,
    int ch, int tid)
{
#pragma unroll
    for (int i = 0; i < 2; i++) {
        int idx = tid + 256 * i;
        int r = idx >> 2, c = idx & 3;
        cp16(stage + r * RSTR + c * 16,
             hA + (rowBase + r) * 1024 + ch * 32 + c * 8);
    }
#pragma unroll
    for (int i = 0; i < 4; i++) {
        int idx = tid + 256 * i;
        int n = idx >> 2, c = idx & 3;
        cp16(stage + (128 + n) * RSTR + c * 16,
             hW + (colBase + n) * 1024 + ch * 32 + c * 8);
    }
}

template <typename OT>
__global__ void __launch_bounds__(256, 1) proj_h(
    const __half* __restrict__ hA, const __half* __restrict__ hW,
    const float* __restrict__ bias, const float* __restrict__ gamma,
    const float* __restrict__ beta, OT* __restrict__ C)
{
    extern __shared__ char smem[];
    const uint32_t sb = smem_u32(smem);

    const int tid  = threadIdx.x;
    const int lane = tid & 31;
    const int wid  = tid >> 5;
    const int wm   = wid >> 2;
    const int wn   = wid & 3;
    const int g    = lane >> 2;
    const int tc   = lane & 3;

    const size_t rowBase = (size_t)blockIdx.y * 128;
    const size_t colBase = (size_t)blockIdx.x * 256;

    float acc[4][8][4];
#pragma unroll
    for (int mt = 0; mt < 4; mt++)
#pragma unroll
        for (int nt = 0; nt < 8; nt++)
#pragma unroll
            for (int z = 0; z < 4; z++) acc[mt][nt][z] = 0.f;

    for (int ch = 0; ch < 3; ch++) {
        proj_issue(sb + ch * STAGE_B, hA, hW, rowBase, colBase, ch, tid);
        CP_COMMIT();
    }

    const uint32_t aAddrBase = (uint32_t)((wm * 64 + (lane & 15)) * RSTR + (lane >> 4) * 16);
    const uint32_t bAddrBase = (uint32_t)((128 + wn * 64 + (lane & 7)) * RSTR + ((lane >> 3) & 1) * 16);

    for (int ch = 0; ch < 32; ch++) {
        CP_WAIT(2);
        __syncthreads();
        if (ch + 3 < 32)
            proj_issue(sb + ((ch + 3) & 3) * STAGE_B, hA, hW, rowBase, colBase,
                       ch + 3, tid);
        CP_COMMIT();

        const uint32_t S = sb + (ch & 3) * STAGE_B;
#pragma unroll
        for (int ks = 0; ks < 2; ks++) {
            uint32_t af[4][4], bf[8][2];
#pragma unroll
            for (int mt = 0; mt < 4; mt++)
                LDSM_X4(af[mt], S + aAddrBase + mt * 16 * RSTR + ks * 32);
#pragma unroll
            for (int nt = 0; nt < 8; nt++)
                LDSM_X2(bf[nt], S + bAddrBase + nt * 8 * RSTR + ks * 32);
#pragma unroll
            for (int mt = 0; mt < 4; mt++)
#pragma unroll
                for (int nt = 0; nt < 8; nt++)
                    MMA_F16(acc[mt][nt], af[mt], bf[nt]);
        }
    }
    CP_WAIT(0);
    __syncthreads();

    /* ---------------- epilogue: bias + celu + groupnorm ------------------ */
    float* SB = (float*)(smem + OFF_SB);
    float* SG = (float*)(smem + OFF_SG);
    float* SE = (float*)(smem + OFF_SE);
    float* RS = (float*)(smem + OFF_RS);
    float* RQ = (float*)(smem + OFF_RQ);

    SB[tid] = bias [colBase + tid];
    SG[tid] = gamma[colBase + tid];
    SE[tid] = beta [colBase + tid];
    __syncthreads();

#pragma unroll
    for (int mt = 0; mt < 4; mt++)
#pragma unroll
        for (int half = 0; half < 2; half++) {
            const int r = wm * 64 + mt * 16 + half * 8 + g;
            float s = 0.f, q = 0.f;
#pragma unroll
            for (int nt = 0; nt < 8; nt++) {
                const int c0 = wn * 64 + nt * 8 + 2 * tc;
                float x0 = acc[mt][nt][half * 2 + 0] + SB[c0];
                float x1 = acc[mt][nt][half * 2 + 1] + SB[c0 + 1];
                x0 = (x0 > 0.f) ? x0 : ALPHA_C * expm1f(x0 * (1.0f / ALPHA_C));
                x1 = (x1 > 0.f) ? x1 : ALPHA_C * expm1f(x1 * (1.0f / ALPHA_C));
                acc[mt][nt][half * 2 + 0] = x0;
                acc[mt][nt][half * 2 + 1] = x1;
                s += x0 + x1; q += x0 * x0 + x1 * x1;
            }
            s += __shfl_xor_sync(0xffffffffu, s, 1);
            s += __shfl_xor_sync(0xffffffffu, s, 2);
            q += __shfl_xor_sync(0xffffffffu, q, 1);
            q += __shfl_xor_sync(0xffffffffu, q, 2);
            if (tc == 0) { RS[r * 4 + wn] = s; RQ[r * 4 + wn] = q; }
        }
    __syncthreads();

    const int gw = (wn >> 1) * 2;
#pragma unroll
    for (int mt = 0; mt < 4; mt++)
#pragma unroll
        for (int half = 0; half < 2; half++) {
            const int r = wm * 64 + mt * 16 + half * 8 + g;
            const float S = RS[r * 4 + gw] + RS[r * 4 + gw + 1];
            const float Q = RQ[r * 4 + gw] + RQ[r * 4 + gw + 1];
            const float mean = S * (1.f / 128.f);
            const float var  = Q * (1.f / 128.f) - mean * mean;
            const float inv  = rsqrtf(var + EPS_C);
            OT* Crow = C + (rowBase + r) * 1024 + colBase;
#pragma unroll
            for (int nt = 0; nt < 8; nt++) {
                const int c0 = wn * 64 + nt * 8 + 2 * tc;
                float ox = (acc[mt][nt][half * 2 + 0] - mean) * inv * SG[c0]     + SE[c0];
                float oy = (acc[mt][nt][half * 2 + 1] - mean) * inv * SG[c0 + 1] + SE[c0 + 1];
                if constexpr (sizeof(OT) == 4) {
                    *(float2*)&Crow[c0] = make_float2(ox, oy);
                } else {
                    *(__half2*)&Crow[c0] = __floats2half2_rn(ox, oy);
                }
            }
        }
}

/* =========================================================================
 * attn_mma: per (b,h) block.
 * Fold q into Wb:  Wq'[o,d] = Wb[o,d] * q[b,h,d]  (f16)
 * h[m,o] = relu(K[m,:] . Wq'[o,:] + bb[o])   via fp16 mma.sync.
 * Emits masked logits (h.Wl + bl) and masked mean pool.
 * 256 threads; K rows streamed 128/iter with 3-stage cp.async pipeline.
 * ========================================================================= */
#define ASTR      272                     /* 128 halfs + 16B pad            */
#define KSTAGE_B  (128 * ASTR)
#define ATTN_SMEM (64 * ASTR + 3 * KSTAGE_B + 8 * 64 * 4 + 16)

__device__ __forceinline__ void attn_issue(uint32_t stage, int mbase,
                                           int b, int h, int tid)
{
#pragma unroll
    for (int i = 0; i < 8; i++) {
        int c = tid + 256 * i;           /* 0..2047 */
        int r = c >> 4, col = c & 15;
        int mg = mbase + r;
        const __half* src;
        if (mg < Mseq) {
            src = g_hKout + ((size_t)(b * Mseq + mg)) * 1024 + h * 128 + col * 8;
        } else {
            int mm = mg - Mseq;
            if (mm >= MEMN) mm = 0;      /* OOB rows: garbage, masked later */
            src = g_hMemK + (size_t)mm * 1024 + h * 128 + col * 8;
        }
        cp16(stage + r * ASTR + col * 16, src);
    }
}

__global__ void __launch_bounds__(256, 1) attn_mma(
    const float* __restrict__ mask, const float* __restrict__ Wb,
    const float* __restrict__ bb, const float* __restrict__ Wl,
    const float* __restrict__ bl)
{
    extern __shared__ char sm[];
    const uint32_t sb = smem_u32(sm);
    const uint32_t WQ = sb;
    const uint32_t KT = sb + 64 * ASTR;
    float* PR  = (float*)(sm + 64 * ASTR + 3 * KSTAGE_B);
    float* MSM = PR + 8 * 64;

    const int bh = blockIdx.x, b = bh >> 3, h = bh & 7;
    const int tid = threadIdx.x;
    const int lane = tid & 31;
    const int wid  = tid >> 5;
    const int g    = lane >> 2;
    const int tc   = lane & 3;

    /* Wq'[o][d] = Wb[o][d] * q[d], f16 into smem */
    const float* qrow = g_q + (size_t)b * 1024 + h * 128;
    for (int idx = tid; idx < 8192; idx += 256) {
        int o = idx >> 7, d = idx & 127;
        float w = Wb[o * 128 + d] * qrow[d];
        *(__half*)(sm + o * ASTR + d * 2) = __float2half(w);
    }
    if (tid < 32) {
        float s = 0.f;
        for (int m = tid; m < MFULL; m += 32) {
            int mm = (m < Mseq) ? m : (m - Mseq);
            s += mask[b * Mseq + mm];
        }
#pragma unroll
        for (int o = 16; o; o >>= 1) s += __shfl_xor_sync(0xffffffffu, s, o);
        if (tid == 0) MSM[0] = s;
    }

    attn_issue(KT + 0 * KSTAGE_B,   0, b, h, tid); CP_COMMIT();
    attn_issue(KT + 1 * KSTAGE_B, 128, b, h, tid); CP_COMMIT();

    float bbf[8][2], wlf[8][2];
#pragma unroll
    for (int nt = 0; nt < 8; nt++) {
        const int c0 = nt * 8 + 2 * tc;
        bbf[nt][0] = bb[c0]; bbf[nt][1] = bb[c0 + 1];
        wlf[nt][0] = Wl[c0]; wlf[nt][1] = Wl[c0 + 1];
    }
    const float bl0 = bl[0];
    const float* maskb = mask + (size_t)b * Mseq;

    float pool[8][2];
#pragma unroll
    for (int nt = 0; nt < 8; nt++) { pool[nt][0] = 0.f; pool[nt][1] = 0.f; }

    const uint32_t aBase = (uint32_t)((wid * 16 + (lane & 15)) * ASTR + (lane >> 4) * 16);
    const uint32_t bBase = (uint32_t)((lane & 7) * ASTR + ((lane >> 3) & 1) * 16);

    for (int it = 0; it < 9; it++) {
        CP_WAIT(1);
        __syncthreads();
        if (it + 2 < 9) {
            attn_issue(KT + ((it + 2) % 3) * KSTAGE_B, (it + 2) * 128, b, h, tid);
            CP_COMMIT();
        }
        const uint32_t S = KT + (it % 3) * KSTAGE_B;

        float acc[8][4];
#pragma unroll
        for (int nt = 0; nt < 8; nt++)
#pragma unroll
            for (int z = 0; z < 4; z++) acc[nt][z] = 0.f;

#pragma unroll
        for (int ks = 0; ks < 8; ks++) {
            uint32_t af[4];
            LDSM_X4(af, S + aBase + ks * 32);
#pragma unroll
            for (int nt = 0; nt < 8; nt++) {
                uint32_t bf[2];
                LDSM_X2(bf, WQ - sb + sb + bBase + nt * 8 * ASTR + ks * 32);
                MMA_F16(acc[nt], af, bf);
            }
        }

        /* epilogue: relu + logits + pool */
        const int mg0 = it * 128 + wid * 16 + g;
        const int mg1 = mg0 + 8;
        float mv0 = 0.f, mv1 = 0.f;
        if (mg0 < MFULL) mv0 = maskb[(mg0 < Mseq) ? mg0 : (mg0 - Mseq)];
        if (mg1 < MFULL) mv1 = maskb[(mg1 < Mseq) ? mg1 : (mg1 - Mseq)];

        float s0 = 0.f, s1 = 0.f;
#pragma unroll
        for (int nt = 0; nt < 8; nt++) {
            float h00 = fmaxf(acc[nt][0] + bbf[nt][0], 0.f);
            float h01 = fmaxf(acc[nt][1] + bbf[nt][1], 0.f);
            float h10 = fmaxf(acc[nt][2] + bbf[nt][0], 0.f);
            float h11 = fmaxf(acc[nt][3] + bbf[nt][1], 0.f);
            s0 += h00 * wlf[nt][0] + h01 * wlf[nt][1];
            s1 += h10 * wlf[nt][0] + h11 * wlf[nt][1];
            pool[nt][0] += h00 * mv0 + h10 * mv1;
            pool[nt][1] += h01 * mv0 + h11 * mv1;
        }
        s0 += __shfl_xor_sync(0xffffffffu, s0, 1);
        s0 += __shfl_xor_sync(0xffffffffu, s0, 2);
        s1 += __shfl_xor_sync(0xffffffffu, s1, 1);
        s1 += __shfl_xor_sync(0xffffffffu, s1, 2);
        if (tc == 0) {
            if (mg0 < MFULL)
                g_logits[(size_t)bh * MFULL + mg0] = (mv0 == 0.f) ? -1e9f : s0 + bl0;
            if (mg1 < MFULL)
                g_logits[(size_t)bh * MFULL + mg1] = (mv1 == 0.f) ? -1e9f : s1 + bl0;
        }
    }

    /* pool reduction: over g lanes (xor 4,8,16), then across warps */
#pragma unroll
    for (int nt = 0; nt < 8; nt++)
#pragma unroll
        for (int c = 0; c < 2; c++) {
            float v = pool[nt][c];
            v += __shfl_xor_sync(0xffffffffu, v, 4);
            v += __shfl_xor_sync(0xffffffffu, v, 8);
            v += __shfl_xor_sync(0xffffffffu, v, 16);
            if (lane < 4) PR[wid * 64 + nt * 8 + 2 * lane + c] = v;
        }
    __syncthreads();
    if (tid < 64) {
        float s = 0.f;
#pragma unroll
        for (int w = 0; w < 8; w++) s += PR[w * 64 + tid];
        g_pool[(size_t)bh * 64 + tid] = s / MSM[0];
    }
}

/* =========================================================================
 * finalize: softmax(logits), alpha_channel = sigmoid(pool@Wl2^T+bl2),
 * v2p = sum_m alpha * v2,  out = v1 * v2p * alpha_channel
 * ========================================================================= */
__global__ void __launch_bounds__(256) finalize_kernel(
    const float* __restrict__ Wl2, const float* __restrict__ bl2,
    float* __restrict__ out)
{
    __shared__ float alpha[MFULL];
    __shared__ float red[256];
    __shared__ float pool_s[64];
    __shared__ float vpart[256];

    const int bh = blockIdx.x, b = bh >> 3, h = bh & 7;
    const int tid = threadIdx.x;

    float mx = -INFINITY;
    for (int m = tid; m < MFULL; m += 256) {
        float l = g_logits[(size_t)bh * MFULL + m];
        alpha[m] = l;
        mx = fmaxf(mx, l);
    }
    red[tid] = mx;
    __syncthreads();
    for (int s = 128; s > 0; s >>= 1) {
        if (tid < s) red[tid] = fmaxf(red[tid], red[tid + s]);
        __syncthreads();
    }
    mx = red[0];
    __syncthreads();

    float es = 0.f;
    for (int m = tid; m < MFULL; m += 256) {
        float e = expf(alpha[m] - mx);
        alpha[m] = e;
        es += e;
    }
    red[tid] = es;
    if (tid < 64) pool_s[tid] = g_pool[(size_t)bh * 64 + tid];
    __syncthreads();
    for (int s = 128; s > 0; s >>= 1) {
        if (tid < s) red[tid] += red[tid + s];
        __syncthreads();
    }
    const float sumExp = red[0];

    const int d = tid & 127, half = tid >> 7;
    float acc = 0.f;
    for (int m = half; m < MFULL; m += 2) {
        float a = alpha[m];
        float v;
        if (m < Mseq)
            v = __half2float(g_hV2out[((size_t)(b * Mseq + m)) * 1024 + h * 128 + d]);
        else
            v = __half2float(g_hMemV[(size_t)(m - Mseq) * 1024 + h * 128 + d]);
        acc += a * v;
    }
    vpart[tid] = acc;
    __syncthreads();

    if (tid < 128) {
        float v2p = (vpart[tid] + vpart[tid + 128]) / sumExp;
        float s = bl2[d];
#pragma unroll
        for (int o = 0; o < 64; o++) s += pool_s[o] * Wl2[d * 64 + o];
        float ac = 1.f / (1.f + expf(-s));
        size_t oidx = (size_t)b * Ee + h * Dd + d;
        out[oidx] = g_v1[oidx] * v2p * ac;
    }
}

/* ========================================================================= */
extern "C" void kernel_launch(void* const* d_in, const int* in_sizes, int n_in,
                              void* d_out, int out_size)
{
    const float* query  = (const float*)d_in[0];
    const float* key    = (const float*)d_in[1];
    const float* mask   = (const float*)d_in[2];
    const float* value1 = (const float*)d_in[3];
    const float* value2 = (const float*)d_in[4];
    const float* Wq  = (const float*)d_in[5];  const float* bq  = (const float*)d_in[6];
    const float* gq  = (const float*)d_in[7];  const float* sq  = (const float*)d_in[8];
    const float* Wk  = (const float*)d_in[9];  const float* bk  = (const float*)d_in[10];
    const float* gk  = (const float*)d_in[11]; const float* sk  = (const float*)d_in[12];
    const float* Wv1 = (const float*)d_in[13]; const float* bv1 = (const float*)d_in[14];
    const float* gv1 = (const float*)d_in[15]; const float* sv1 = (const float*)d_in[16];
    const float* Wv2 = (const float*)d_in[17]; const float* bv2 = (const float*)d_in[18];
    const float* gv2 = (const float*)d_in[19]; const float* sv2 = (const float*)d_in[20];
    const float* mem = (const float*)d_in[21];
    const float* Wb  = (const float*)d_in[22]; const float* bb  = (const float*)d_in[23];
    const float* Wl  = (const float*)d_in[24]; const float* bl  = (const float*)d_in[25];
    const float* Wl2 = (const float*)d_in[26]; const float* bl2 = (const float*)d_in[27];
    float* out = (float*)d_out;

    void *pq, *pv1;
    cudaGetSymbolAddress(&pq,  g_q);
    cudaGetSymbolAddress(&pv1, g_v1);
    void *phKey, *phV2in, *phKout, *phV2out, *phQ, *phV1;
    void *phWq, *phWk, *phWv1, *phWv2, *phMemK, *phMemV;
    cudaGetSymbolAddress(&phKey,  g_hKey);
    cudaGetSymbolAddress(&phV2in, g_hV2in);
    cudaGetSymbolAddress(&phKout, g_hKout);
    cudaGetSymbolAddress(&phV2out,g_hV2out);
    cudaGetSymbolAddress(&phQ,    g_hQin);
    cudaGetSymbolAddress(&phV1,   g_hV1in);
    cudaGetSymbolAddress(&phWq,   g_hWq);
    cudaGetSymbolAddress(&phWk,   g_hWk);
    cudaGetSymbolAddress(&phWv1,  g_hWv1);
    cudaGetSymbolAddress(&phWv2,  g_hWv2);
    cudaGetSymbolAddress(&phMemK, g_hMemK);
    cudaGetSymbolAddress(&phMemV, g_hMemV);

    cudaFuncSetAttribute(proj_h<float>,
                         cudaFuncAttributeMaxDynamicSharedMemorySize, PROJ_SMEM);
    cudaFuncSetAttribute(proj_h<__half>,
                         cudaFuncAttributeMaxDynamicSharedMemorySize, PROJ_SMEM);
    cudaFuncSetAttribute(attn_mma,
                         cudaFuncAttributeMaxDynamicSharedMemorySize, ATTN_SMEM);

    /* f32 -> f16 pre-pass */
    const int BIGN8 = (int)(((size_t)Bq * Mseq * Ee) / 8);
    cvt_f16_kernel<<<4096, 256>>>((const float4*)key,    (uint4*)phKey,  BIGN8);
    cvt_f16_kernel<<<4096, 256>>>((const float4*)value2, (uint4*)phV2in, BIGN8);
    cvt_f16_kernel<<<128,  256>>>((const float4*)query,  (uint4*)phQ,    Bq * Ee / 8);
    cvt_f16_kernel<<<128,  256>>>((const float4*)value1, (uint4*)phV1,   Bq * Ee / 8);
    cvt_f16_kernel<<<512,  256>>>((const float4*)Wq,  (uint4*)phWq,  Ee * Ee / 8);
    cvt_f16_kernel<<<512,  256>>>((const float4*)Wk,  (uint4*)phWk,  Ee * Ee / 8);
    cvt_f16_kernel<<<512,  256>>>((const float4*)Wv1, (uint4*)phWv1, Ee * Ee / 8);
    cvt_f16_kernel<<<512,  256>>>((const float4*)Wv2, (uint4*)phWv2, Ee * Ee / 8);
    cvt_mem_kernel<<<40, 256>>>(mem, (__half*)phMemK, (__half*)phMemV, MEMN * Ee);

    /* projections on fp16 mma.sync tensor cores */
    proj_h<float><<<dim3(4, 1), 256, PROJ_SMEM>>>(
        (const __half*)phQ,  (const __half*)phWq,  bq,  gq,  sq,  (float*)pq);
    proj_h<float><<<dim3(4, 1), 256, PROJ_SMEM>>>(
        (const __half*)phV1, (const __half*)phWv1, bv1, gv1, sv1, (float*)pv1);
    proj_h<__half><<<dim3(4, 1024), 256, PROJ_SMEM>>>(
        (const __half*)phKey,  (const __half*)phWk,  bk,  gk,  sk,  (__half*)phKout);
    proj_h<__half><<<dim3(4, 1024), 256, PROJ_SMEM>>>(
        (const __half*)phV2in, (const __half*)phWv2, bv2, gv2, sv2, (__half*)phV2out);

    /* per-(b,h) low-rank scoring on tensor cores: logits + pool */
    attn_mma<<<Bq * Hh, 256, ATTN_SMEM>>>(mask, Wb, bb, Wl, bl);

    /* softmax + channel gate + weighted sum + output */
    finalize_kernel<<<Bq * Hh, 256>>>(Wl2, bl2, out);
}

// round 8
// speedup vs baseline: 5.7839x; 1.1408x over previous
#include <cuda_runtime.h>
#include <cuda_fp16.h>
#include <math.h>
#include <stdint.h>

#define Bq    128
#define Mseq  1024
#define Ee    1024
#define Hh    8
#define Dd    128
#define MEMN  40
#define MFULL 1064
#define MIDN  64
#define ALPHA_C 1.3f
#define EPS_C   1e-5f
#define SQRT_D_C    11.313708498984760390f   /* sqrt(128) */
#define SQRT_MEM_C  6.3245553203367586640f   /* sqrt(40)  */

/* ---------------- scratch (static device memory: allowed) ---------------- */
__device__ float  g_q   [Bq * Ee];
__device__ float  g_v1  [Bq * Ee];
__device__ float  g_pool[Bq * Hh * MIDN];
__device__ float  g_logits[Bq * Hh * MFULL];

__device__ __half g_hKey [(size_t)Bq * Mseq * Ee]; /* f16 key input    */
__device__ __half g_hV2in[(size_t)Bq * Mseq * Ee]; /* f16 value2 input */
__device__ __half g_hKout[(size_t)Bq * Mseq * Ee]; /* projected K f16  */
__device__ __half g_hV2out[(size_t)Bq * Mseq * Ee];/* projected V2 f16 */
__device__ __half g_hQin [Bq * Ee];
__device__ __half g_hV1in[Bq * Ee];
__device__ __half g_hWq [Ee * Ee];
__device__ __half g_hWk [Ee * Ee];
__device__ __half g_hWv1[Ee * Ee];
__device__ __half g_hWv2[Ee * Ee];
__device__ __half g_hMemK[MEMN * Ee];              /* sqrt(D)  * mem   */
__device__ __half g_hMemV[MEMN * Ee];              /* sqrt(MEM)* mem   */

/* ======================= helpers =========================== */
__device__ __forceinline__ uint32_t smem_u32(const void* p) {
    uint32_t a;
    asm("{ .reg .u64 t; cvta.to.shared.u64 t, %1; cvt.u32.u64 %0, t; }"
        : "=r"(a) : "l"(p));
    return a;
}
__device__ __forceinline__ void cp16(uint32_t s, const void* g) {
    asm volatile("cp.async.ca.shared.global [%0], [%1], 16;"
                 :: "r"(s), "l"(g) : "memory");
}
#define CP_COMMIT() asm volatile("cp.async.commit_group;" ::: "memory")
#define CP_WAIT(n)  asm volatile("cp.async.wait_group %0;" :: "n"(n) : "memory")

#define LDSM_X4(r, a)                                                        \
    asm volatile("ldmatrix.sync.aligned.m8n8.x4.shared.b16 {%0,%1,%2,%3}, [%4];" \
        : "=r"((r)[0]), "=r"((r)[1]), "=r"((r)[2]), "=r"((r)[3]) : "r"(a))
#define LDSM_X2(r, a)                                                        \
    asm volatile("ldmatrix.sync.aligned.m8n8.x2.shared.b16 {%0,%1}, [%2];"   \
        : "=r"((r)[0]), "=r"((r)[1]) : "r"(a))

#define MMA_F16(d, a, b)                                                     \
    asm volatile("mma.sync.aligned.m16n8k16.row.col.f32.f16.f16.f32 "        \
        "{%0,%1,%2,%3}, {%4,%5,%6,%7}, {%8,%9}, {%0,%1,%2,%3};"              \
        : "+f"((d)[0]), "+f"((d)[1]), "+f"((d)[2]), "+f"((d)[3])             \
        : "r"((a)[0]), "r"((a)[1]), "r"((a)[2]), "r"((a)[3]),                \
          "r"((b)[0]), "r"((b)[1]))

/* ---------------- f32 -> f16 conversion pre-pass ---------------- */
__device__ __forceinline__ void cvt_loop(const float4* __restrict__ in,
                                         uint4* __restrict__ out, int n8)
{
    for (int i = blockIdx.x * blockDim.x + threadIdx.x; i < n8;
         i += gridDim.x * blockDim.x) {
        float4 a = in[2 * i], b = in[2 * i + 1];
        __half2 h0 = __floats2half2_rn(a.x, a.y);
        __half2 h1 = __floats2half2_rn(a.z, a.w);
        __half2 h2 = __floats2half2_rn(b.x, b.y);
        __half2 h3 = __floats2half2_rn(b.z, b.w);
        out[i] = make_uint4(*(uint32_t*)&h0, *(uint32_t*)&h1,
                            *(uint32_t*)&h2, *(uint32_t*)&h3);
    }
}
__global__ void __launch_bounds__(256) cvt_f16_kernel(
    const float4* __restrict__ in, uint4* __restrict__ out, int n8)
{
    cvt_loop(in, out, n8);
}
/* 4 weight matrices in one launch (blockIdx.y selects) */
__global__ void __launch_bounds__(256) cvt_w4_kernel(
    const float4* w0, const float4* w1, const float4* w2, const float4* w3,
    uint4* o0, uint4* o1, uint4* o2, uint4* o3, int n8)
{
    const float4* in; uint4* out;
    switch (blockIdx.y) {
        case 0:  in = w0; out = o0; break;
        case 1:  in = w1; out = o1; break;
        case 2:  in = w2; out = o2; break;
        default: in = w3; out = o3; break;
    }
    cvt_loop(in, out, n8);
}
__global__ void __launch_bounds__(256) cvt_qv_kernel(
    const float4* a0, const float4* a1, uint4* o0, uint4* o1, int n8)
{
    cvt_loop(blockIdx.y ? a1 : a0, blockIdx.y ? o1 : o0, n8);
}
__global__ void __launch_bounds__(256) cvt_mem_kernel(
    const float* __restrict__ mem, __half* __restrict__ mk,
    __half* __restrict__ mv, int n)
{
    for (int i = blockIdx.x * blockDim.x + threadIdx.x; i < n;
         i += gridDim.x * blockDim.x) {
        float m = mem[i];
        mk[i] = __float2half(m * SQRT_D_C);
        mv[i] = __float2half(m * SQRT_MEM_C);
    }
}

/* =========================================================================
 * proj_h: C = groupnorm(celu(A @ W^T + bias)), fp16 mma.sync m16n8k16.
 * CTA tile 128(M) x 256(N), BK=64, 8 warps (2x4) of 64x64 warp tiles.
 * 3-stage cp.async pipeline (2 in flight), 16 K-chunks (half the barriers
 * of the BK=32 version). Smem row stride 144B: conflict-free ldmatrix.
 * Output type templated: f32 (q, v1) or f16 (K, V2).
 * ========================================================================= */
#define RSTR    144                      /* 64 halves + 16B pad            */
#define STAGE_B (384 * RSTR)             /* 128 A rows + 256 W rows        */
#define OFF_SB  (3 * STAGE_B)
#define OFF_SG  (OFF_SB + 1024)
#define OFF_SE  (OFF_SG + 1024)
#define OFF_RS  (OFF_SE + 1024)
#define OFF_RQ  (OFF_RS + 2048)
#define PROJ_SMEM (OFF_RQ + 2048)        /* 173056 bytes */

__device__ __forceinline__ void proj_issue(
    uint32_t stage, const __half* __restrict__ hA,
    const __half* __restrict__ hW, size_t rowBase, size_t colBase,
    int ch, int tid)
{
#pragma unroll
    for (int i = 0; i < 4; i++) {
        int idx = tid + 256 * i;         /* 0..1023 : A 128 rows x 8 cp16 */
        int r = idx >> 3, c = idx & 7;
        cp16(stage + r * RSTR + c * 16,
             hA + (rowBase + r) * 1024 + ch * 64 + c * 8);
    }
#pragma unroll
    for (int i = 0; i < 8; i++) {
        int idx = tid + 256 * i;         /* 0..2047 : W 256 rows x 8 cp16 */
        int n = idx >> 3, c = idx & 7;
        cp16(stage + (128 + n) * RSTR + c * 16,
             hW + (colBase + n) * 1024 + ch * 64 + c * 8);
    }
}

template <typename OT>
__global__ void __launch_bounds__(256, 1) proj_h(
    const __half* __restrict__ hA, const __half* __restrict__ hW,
    const float* __restrict__ bias, const float* __restrict__ gamma,
    const float* __restrict__ beta, OT* __restrict__ C)
{
    extern __shared__ char smem[];
    const uint32_t sb = smem_u32(smem);

    const int tid  = threadIdx.x;
    const int lane = tid & 31;
    const int wid  = tid >> 5;
    const int wm   = wid >> 2;
    const int wn   = wid & 3;
    const int g    = lane >> 2;
    const int tc   = lane & 3;

    const size_t rowBase = (size_t)blockIdx.y * 128;
    const size_t colBase = (size_t)blockIdx.x * 256;

    float acc[4][8][4];
#pragma unroll
    for (int mt = 0; mt < 4; mt++)
#pragma unroll
        for (int nt = 0; nt < 8; nt++)
#pragma unroll
            for (int z = 0; z < 4; z++) acc[mt][nt][z] = 0.f;

    proj_issue(sb + 0 * STAGE_B, hA, hW, rowBase, colBase, 0, tid); CP_COMMIT();
    proj_issue(sb + 1 * STAGE_B, hA, hW, rowBase, colBase, 1, tid); CP_COMMIT();

    const uint32_t aAddrBase = (uint32_t)((wm * 64 + (lane & 15)) * RSTR + (lane >> 4) * 16);
    const uint32_t bAddrBase = (uint32_t)((128 + wn * 64 + (lane & 7)) * RSTR + ((lane >> 3) & 1) * 16);

    int slot = 0;
    for (int ch = 0; ch < 16; ch++) {
        CP_WAIT(1);
        __syncthreads();
        if (ch + 2 < 16) {
            int ns = slot + 2; if (ns >= 3) ns -= 3;
            proj_issue(sb + ns * STAGE_B, hA, hW, rowBase, colBase, ch + 2, tid);
        }
        CP_COMMIT();

        const uint32_t S = sb + slot * STAGE_B;
        if (++slot == 3) slot = 0;
#pragma unroll
        for (int ks = 0; ks < 4; ks++) {
            uint32_t af[4][4], bf[8][2];
#pragma unroll
            for (int mt = 0; mt < 4; mt++)
                LDSM_X4(af[mt], S + aAddrBase + mt * 16 * RSTR + ks * 32);
#pragma unroll
            for (int nt = 0; nt < 8; nt++)
                LDSM_X2(bf[nt], S + bAddrBase + nt * 8 * RSTR + ks * 32);
#pragma unroll
            for (int mt = 0; mt < 4; mt++)
#pragma unroll
                for (int nt = 0; nt < 8; nt++)
                    MMA_F16(acc[mt][nt], af[mt], bf[nt]);
        }
    }
    CP_WAIT(0);
    __syncthreads();

    /* ---------------- epilogue: bias + celu + groupnorm ------------------ */
    float* SB = (float*)(smem + OFF_SB);
    float* SG = (float*)(smem + OFF_SG);
    float* SE = (float*)(smem + OFF_SE);
    float* RS = (float*)(smem + OFF_RS);
    float* RQ = (float*)(smem + OFF_RQ);

    SB[tid] = bias [colBase + tid];
    SG[tid] = gamma[colBase + tid];
    SE[tid] = beta [colBase + tid];
    __syncthreads();

#pragma unroll
    for (int mt = 0; mt < 4; mt++)
#pragma unroll
        for (int half = 0; half < 2; half++) {
            const int r = wm * 64 + mt * 16 + half * 8 + g;
            float s = 0.f, q = 0.f;
#pragma unroll
            for (int nt = 0; nt < 8; nt++) {
                const int c0 = wn * 64 + nt * 8 + 2 * tc;
                float x0 = acc[mt][nt][half * 2 + 0] + SB[c0];
                float x1 = acc[mt][nt][half * 2 + 1] + SB[c0 + 1];
                x0 = (x0 > 0.f) ? x0 : ALPHA_C * expm1f(x0 * (1.0f / ALPHA_C));
                x1 = (x1 > 0.f) ? x1 : ALPHA_C * expm1f(x1 * (1.0f / ALPHA_C));
                acc[mt][nt][half * 2 + 0] = x0;
                acc[mt][nt][half * 2 + 1] = x1;
                s += x0 + x1; q += x0 * x0 + x1 * x1;
            }
            s += __shfl_xor_sync(0xffffffffu, s, 1);
            s += __shfl_xor_sync(0xffffffffu, s, 2);
            q += __shfl_xor_sync(0xffffffffu, q, 1);
            q += __shfl_xor_sync(0xffffffffu, q, 2);
            if (tc == 0) { RS[r * 4 + wn] = s; RQ[r * 4 + wn] = q; }
        }
    __syncthreads();

    const int gw = (wn >> 1) * 2;
#pragma unroll
    for (int mt = 0; mt < 4; mt++)
#pragma unroll
        for (int half = 0; half < 2; half++) {
            const int r = wm * 64 + mt * 16 + half * 8 + g;
            const float S = RS[r * 4 + gw] + RS[r * 4 + gw + 1];
            const float Q = RQ[r * 4 + gw] + RQ[r * 4 + gw + 1];
            const float mean = S * (1.f / 128.f);
            const float var  = Q * (1.f / 128.f) - mean * mean;
            const float inv  = rsqrtf(var + EPS_C);
            OT* Crow = C + (rowBase + r) * 1024 + colBase;
#pragma unroll
            for (int nt = 0; nt < 8; nt++) {
                const int c0 = wn * 64 + nt * 8 + 2 * tc;
                float ox = (acc[mt][nt][half * 2 + 0] - mean) * inv * SG[c0]     + SE[c0];
                float oy = (acc[mt][nt][half * 2 + 1] - mean) * inv * SG[c0 + 1] + SE[c0 + 1];
                if constexpr (sizeof(OT) == 4) {
                    *(float2*)&Crow[c0] = make_float2(ox, oy);
                } else {
                    *(__half2*)&Crow[c0] = __floats2half2_rn(ox, oy);
                }
            }
        }
}

/* =========================================================================
 * attn_mma: per (b,h) block.
 * Fold q into Wb:  Wq'[o,d] = Wb[o,d] * q[b,h,d]  (f16)
 * h[m,o] = relu(K[m,:] . Wq'[o,:] + bb[o])   via fp16 mma.sync.
 * Emits masked logits (h.Wl + bl) and masked mean pool.
 * ========================================================================= */
#define ASTR      272                     /* 128 halfs + 16B pad            */
#define KSTAGE_B  (128 * ASTR)
#define ATTN_SMEM (64 * ASTR + 3 * KSTAGE_B + 8 * 64 * 4 + 16)

__device__ __forceinline__ void attn_issue(uint32_t stage, int mbase,
                                           int b, int h, int tid)
{
#pragma unroll
    for (int i = 0; i < 8; i++) {
        int c = tid + 256 * i;           /* 0..2047 */
        int r = c >> 4, col = c & 15;
        int mg = mbase + r;
        const __half* src;
        if (mg < Mseq) {
            src = g_hKout + ((size_t)(b * Mseq + mg)) * 1024 + h * 128 + col * 8;
        } else {
            int mm = mg - Mseq;
            if (mm >= MEMN) mm = 0;      /* OOB rows: garbage, masked later */
            src = g_hMemK + (size_t)mm * 1024 + h * 128 + col * 8;
        }
        cp16(stage + r * ASTR + col * 16, src);
    }
}

__global__ void __launch_bounds__(256, 1) attn_mma(
    const float* __restrict__ mask, const float* __restrict__ Wb,
    const float* __restrict__ bb, const float* __restrict__ Wl,
    const float* __restrict__ bl)
{
    extern __shared__ char sm[];
    const uint32_t sb = smem_u32(sm);
    const uint32_t WQ = sb;
    const uint32_t KT = sb + 64 * ASTR;
    float* PR  = (float*)(sm + 64 * ASTR + 3 * KSTAGE_B);
    float* MSM = PR + 8 * 64;

    const int bh = blockIdx.x, b = bh >> 3, h = bh & 7;
    const int tid = threadIdx.x;
    const int lane = tid & 31;
    const int wid  = tid >> 5;
    const int g    = lane >> 2;
    const int tc   = lane & 3;

    /* Wq'[o][d] = Wb[o][d] * q[d], f16 into smem */
    const float* qrow = g_q + (size_t)b * 1024 + h * 128;
    for (int idx = tid; idx < 8192; idx += 256) {
        int o = idx >> 7, d = idx & 127;
        float w = Wb[o * 128 + d] * qrow[d];
        *(__half*)(sm + o * ASTR + d * 2) = __float2half(w);
    }
    if (tid < 32) {
        float s = 0.f;
        for (int m = tid; m < MFULL; m += 32) {
            int mm = (m < Mseq) ? m : (m - Mseq);
            s += mask[b * Mseq + mm];
        }
#pragma unroll
        for (int o = 16; o; o >>= 1) s += __shfl_xor_sync(0xffffffffu, s, o);
        if (tid == 0) MSM[0] = s;
    }

    attn_issue(KT + 0 * KSTAGE_B,   0, b, h, tid); CP_COMMIT();
    attn_issue(KT + 1 * KSTAGE_B, 128, b, h, tid); CP_COMMIT();

    float bbf[8][2], wlf[8][2];
#pragma unroll
    for (int nt = 0; nt < 8; nt++) {
        const int c0 = nt * 8 + 2 * tc;
        bbf[nt][0] = bb[c0]; bbf[nt][1] = bb[c0 + 1];
        wlf[nt][0] = Wl[c0]; wlf[nt][1] = Wl[c0 + 1];
    }
    const float bl0 = bl[0];
    const float* maskb = mask + (size_t)b * Mseq;

    float pool[8][2];
#pragma unroll
    for (int nt = 0; nt < 8; nt++) { pool[nt][0] = 0.f; pool[nt][1] = 0.f; }

    const uint32_t aBase = (uint32_t)((wid * 16 + (lane & 15)) * ASTR + (lane >> 4) * 16);
    const uint32_t bBase = (uint32_t)((lane & 7) * ASTR + ((lane >> 3) & 1) * 16);

    for (int it = 0; it < 9; it++) {
        CP_WAIT(1);
        __syncthreads();
        if (it + 2 < 9) {
            attn_issue(KT + ((it + 2) % 3) * KSTAGE_B, (it + 2) * 128, b, h, tid);
            CP_COMMIT();
        }
        const uint32_t S = KT + (it % 3) * KSTAGE_B;

        float acc[8][4];
#pragma unroll
        for (int nt = 0; nt < 8; nt++)
#pragma unroll
            for (int z = 0; z < 4; z++) acc[nt][z] = 0.f;

#pragma unroll
        for (int ks = 0; ks < 8; ks++) {
            uint32_t af[4];
            LDSM_X4(af, S + aBase + ks * 32);
#pragma unroll
            for (int nt = 0; nt < 8; nt++) {
                uint32_t bf[2];
                LDSM_X2(bf, WQ + bBase + nt * 8 * ASTR + ks * 32);
                MMA_F16(acc[nt], af, bf);
            }
        }

        /* epilogue: relu + logits + pool */
        const int mg0 = it * 128 + wid * 16 + g;
        const int mg1 = mg0 + 8;
        float mv0 = 0.f, mv1 = 0.f;
        if (mg0 < MFULL) mv0 = maskb[(mg0 < Mseq) ? mg0 : (mg0 - Mseq)];
        if (mg1 < MFULL) mv1 = maskb[(mg1 < Mseq) ? mg1 : (mg1 - Mseq)];

        float s0 = 0.f, s1 = 0.f;
#pragma unroll
        for (int nt = 0; nt < 8; nt++) {
            float h00 = fmaxf(acc[nt][0] + bbf[nt][0], 0.f);
            float h01 = fmaxf(acc[nt][1] + bbf[nt][1], 0.f);
            float h10 = fmaxf(acc[nt][2] + bbf[nt][0], 0.f);
            float h11 = fmaxf(acc[nt][3] + bbf[nt][1], 0.f);
            s0 += h00 * wlf[nt][0] + h01 * wlf[nt][1];
            s1 += h10 * wlf[nt][0] + h11 * wlf[nt][1];
            pool[nt][0] += h00 * mv0 + h10 * mv1;
            pool[nt][1] += h01 * mv0 + h11 * mv1;
        }
        s0 += __shfl_xor_sync(0xffffffffu, s0, 1);
        s0 += __shfl_xor_sync(0xffffffffu, s0, 2);
        s1 += __shfl_xor_sync(0xffffffffu, s1, 1);
        s1 += __shfl_xor_sync(0xffffffffu, s1, 2);
        if (tc == 0) {
            if (mg0 < MFULL)
                g_logits[(size_t)bh * MFULL + mg0] = (mv0 == 0.f) ? -1e9f : s0 + bl0;
            if (mg1 < MFULL)
                g_logits[(size_t)bh * MFULL + mg1] = (mv1 == 0.f) ? -1e9f : s1 + bl0;
        }
    }

    /* pool reduction */
#pragma unroll
    for (int nt = 0; nt < 8; nt++)
#pragma unroll
        for (int c = 0; c < 2; c++) {
            float v = pool[nt][c];
            v += __shfl_xor_sync(0xffffffffu, v, 4);
            v += __shfl_xor_sync(0xffffffffu, v, 8);
            v += __shfl_xor_sync(0xffffffffu, v, 16);
            if (lane < 4) PR[wid * 64 + nt * 8 + 2 * lane + c] = v;
        }
    __syncthreads();
    if (tid < 64) {
        float s = 0.f;
#pragma unroll
        for (int w = 0; w < 8; w++) s += PR[w * 64 + tid];
        g_pool[(size_t)bh * 64 + tid] = s / MSM[0];
    }
}

/* =========================================================================
 * finalize: softmax(logits), alpha_channel = sigmoid(pool@Wl2^T+bl2),
 * v2p = sum_m alpha * v2,  out = v1 * v2p * alpha_channel
 * ========================================================================= */
__global__ void __launch_bounds__(256) finalize_kernel(
    const float* __restrict__ Wl2, const float* __restrict__ bl2,
    float* __restrict__ out)
{
    __shared__ float alpha[MFULL];
    __shared__ float red[256];
    __shared__ float pool_s[64];
    __shared__ float vpart[256];

    const int bh = blockIdx.x, b = bh >> 3, h = bh & 7;
    const int tid = threadIdx.x;

    float mx = -INFINITY;
    for (int m = tid; m < MFULL; m += 256) {
        float l = g_logits[(size_t)bh * MFULL + m];
        alpha[m] = l;
        mx = fmaxf(mx, l);
    }
    red[tid] = mx;
    __syncthreads();
    for (int s = 128; s > 0; s >>= 1) {
        if (tid < s) red[tid] = fmaxf(red[tid], red[tid + s]);
        __syncthreads();
    }
    mx = red[0];
    __syncthreads();

    float es = 0.f;
    for (int m = tid; m < MFULL; m += 256) {
        float e = expf(alpha[m] - mx);
        alpha[m] = e;
        es += e;
    }
    red[tid] = es;
    if (tid < 64) pool_s[tid] = g_pool[(size_t)bh * 64 + tid];
    __syncthreads();
    for (int s = 128; s > 0; s >>= 1) {
        if (tid < s) red[tid] += red[tid + s];
        __syncthreads();
    }
    const float sumExp = red[0];

    const int d = tid & 127, half = tid >> 7;
    float acc = 0.f;
    for (int m = half; m < MFULL; m += 2) {
        float a = alpha[m];
        float v;
        if (m < Mseq)
            v = __half2float(g_hV2out[((size_t)(b * Mseq + m)) * 1024 + h * 128 + d]);
        else
            v = __half2float(g_hMemV[(size_t)(m - Mseq) * 1024 + h * 128 + d]);
        acc += a * v;
    }
    vpart[tid] = acc;
    __syncthreads();

    if (tid < 128) {
        float v2p = (vpart[tid] + vpart[tid + 128]) / sumExp;
        float s = bl2[d];
#pragma unroll
        for (int o = 0; o < 64; o++) s += pool_s[o] * Wl2[d * 64 + o];
        float ac = 1.f / (1.f + expf(-s));
        size_t oidx = (size_t)b * Ee + h * Dd + d;
        out[oidx] = g_v1[oidx] * v2p * ac;
    }
}

/* ========================================================================= */
extern "C" void kernel_launch(void* const* d_in, const int* in_sizes, int n_in,
                              void* d_out, int out_size)
{
    const float* query  = (const float*)d_in[0];
    const float* key    = (const float*)d_in[1];
    const float* mask   = (const float*)d_in[2];
    const float* value1 = (const float*)d_in[3];
    const float* value2 = (const float*)d_in[4];
    const float* Wq  = (const float*)d_in[5];  const float* bq  = (const float*)d_in[6];
    const float* gq  = (const float*)d_in[7];  const float* sq  = (const float*)d_in[8];
    const float* Wk  = (const float*)d_in[9];  const float* bk  = (const float*)d_in[10];
    const float* gk  = (const float*)d_in[11]; const float* sk  = (const float*)d_in[12];
    const float* Wv1 = (const float*)d_in[13]; const float* bv1 = (const float*)d_in[14];
    const float* gv1 = (const float*)d_in[15]; const float* sv1 = (const float*)d_in[16];
    const float* Wv2 = (const float*)d_in[17]; const float* bv2 = (const float*)d_in[18];
    const float* gv2 = (const float*)d_in[19]; const float* sv2 = (const float*)d_in[20];
    const float* mem = (const float*)d_in[21];
    const float* Wb  = (const float*)d_in[22]; const float* bb  = (const float*)d_in[23];
    const float* Wl  = (const float*)d_in[24]; const float* bl  = (const float*)d_in[25];
    const float* Wl2 = (const float*)d_in[26]; const float* bl2 = (const float*)d_in[27];
    float* out = (float*)d_out;

    void *pq, *pv1;
    cudaGetSymbolAddress(&pq,  g_q);
    cudaGetSymbolAddress(&pv1, g_v1);
    void *phKey, *phV2in, *phKout, *phV2out, *phQ, *phV1;
    void *phWq, *phWk, *phWv1, *phWv2, *phMemK, *phMemV;
    cudaGetSymbolAddress(&phKey,  g_hKey);
    cudaGetSymbolAddress(&phV2in, g_hV2in);
    cudaGetSymbolAddress(&phKout, g_hKout);
    cudaGetSymbolAddress(&phV2out,g_hV2out);
    cudaGetSymbolAddress(&phQ,    g_hQin);
    cudaGetSymbolAddress(&phV1,   g_hV1in);
    cudaGetSymbolAddress(&phWq,   g_hWq);
    cudaGetSymbolAddress(&phWk,   g_hWk);
    cudaGetSymbolAddress(&phWv1,  g_hWv1);
    cudaGetSymbolAddress(&phWv2,  g_hWv2);
    cudaGetSymbolAddress(&phMemK, g_hMemK);
    cudaGetSymbolAddress(&phMemV, g_hMemV);

    cudaFuncSetAttribute(proj_h<float>,
                         cudaFuncAttributeMaxDynamicSharedMemorySize, PROJ_SMEM);
    cudaFuncSetAttribute(proj_h<__half>,
                         cudaFuncAttributeMaxDynamicSharedMemorySize, PROJ_SMEM);
    cudaFuncSetAttribute(attn_mma,
                         cudaFuncAttributeMaxDynamicSharedMemorySize, ATTN_SMEM);

    const int BIGN8 = (int)(((size_t)Bq * Mseq * Ee) / 8);

    /* launch 0: all four weight conversions */
    cvt_w4_kernel<<<dim3(512, 4), 256>>>(
        (const float4*)Wq, (const float4*)Wk, (const float4*)Wv1, (const float4*)Wv2,
        (uint4*)phWq, (uint4*)phWk, (uint4*)phWv1, (uint4*)phWv2, Ee * Ee / 8);
    /* launch 1: key f32->f16 */
    cvt_f16_kernel<<<4096, 256>>>((const float4*)key, (uint4*)phKey, BIGN8);
    /* launch 2: K projection  <-- ncu-profiled slot */
    proj_h<__half><<<dim3(4, 1024), 256, PROJ_SMEM>>>(
        (const __half*)phKey, (const __half*)phWk, bk, gk, sk, (__half*)phKout);
    /* launch 3: value2 f32->f16 */
    cvt_f16_kernel<<<4096, 256>>>((const float4*)value2, (uint4*)phV2in, BIGN8);
    /* launch 4: V2 projection */
    proj_h<__half><<<dim3(4, 1024), 256, PROJ_SMEM>>>(
        (const __half*)phV2in, (const __half*)phWv2, bv2, gv2, sv2, (__half*)phV2out);
    /* launch 5: query+value1 conversion */
    cvt_qv_kernel<<<dim3(128, 2), 256>>>(
        (const float4*)query, (const float4*)value1,
        (uint4*)phQ, (uint4*)phV1, Bq * Ee / 8);
    /* launch 6: mem scaling */
    cvt_mem_kernel<<<40, 256>>>(mem, (__half*)phMemK, (__half*)phMemV, MEMN * Ee);
    /* launches 7,8: small projections */
    proj_h<float><<<dim3(4, 1), 256, PROJ_SMEM>>>(
        (const __half*)phQ,  (const __half*)phWq,  bq,  gq,  sq,  (float*)pq);
    proj_h<float><<<dim3(4, 1), 256, PROJ_SMEM>>>(
        (const __half*)phV1, (const __half*)phWv1, bv1, gv1, sv1, (float*)pv1);
    /* launch 9: low-rank scoring */
    attn_mma<<<Bq * Hh, 256, ATTN_SMEM>>>(mask, Wb, bb, Wl, bl);
    /* launch 10: softmax + gate + weighted sum */
    finalize_kernel<<<Bq * Hh, 256>>>(Wl2, bl2, out);
}

// round 9
// speedup vs baseline: 5.8422x; 1.0101x over previous
#include <cuda_runtime.h>
#include <cuda_fp16.h>
#include <math.h>
#include <stdint.h>

#define Bq    128
#define Mseq  1024
#define Ee    1024
#define Hh    8
#define Dd    128
#define MEMN  40
#define MFULL 1064
#define MIDN  64
#define ALPHA_C 1.3f
#define EPS_C   1e-5f
#define SQRT_D_C    11.313708498984760390f   /* sqrt(128) */
#define SQRT_MEM_C  6.3245553203367586640f   /* sqrt(40)  */

/* ---------------- scratch (static device memory: allowed) ---------------- */
__device__ float  g_q   [Bq * Ee];
__device__ float  g_v1  [Bq * Ee];
__device__ float  g_pool[Bq * Hh * MIDN];
__device__ float  g_logits[Bq * Hh * MFULL];

__device__ __half g_hKey [(size_t)Bq * Mseq * Ee]; /* f16 key input    */
__device__ __half g_hV2in[(size_t)Bq * Mseq * Ee]; /* f16 value2 input */
__device__ __half g_hKout[(size_t)Bq * Mseq * Ee]; /* projected K f16  */
__device__ __half g_hV2out[(size_t)Bq * Mseq * Ee];/* projected V2 f16 */
__device__ __half g_hQin [Bq * Ee];
__device__ __half g_hV1in[Bq * Ee];
__device__ __half g_hWq [Ee * Ee];
__device__ __half g_hWk [Ee * Ee];
__device__ __half g_hWv1[Ee * Ee];
__device__ __half g_hWv2[Ee * Ee];
__device__ __half g_hMemK[MEMN * Ee];              /* sqrt(D)  * mem   */
__device__ __half g_hMemV[MEMN * Ee];              /* sqrt(MEM)* mem   */

/* ======================= helpers =========================== */
__device__ __forceinline__ uint32_t smem_u32(const void* p) {
    uint32_t a;
    asm("{ .reg .u64 t; cvta.to.shared.u64 t, %1; cvt.u32.u64 %0, t; }"
        : "=r"(a) : "l"(p));
    return a;
}
__device__ __forceinline__ void cp16(uint32_t s, const void* g) {
    asm volatile("cp.async.ca.shared.global [%0], [%1], 16;"
                 :: "r"(s), "l"(g) : "memory");
}
#define CP_COMMIT() asm volatile("cp.async.commit_group;" ::: "memory")
#define CP_WAIT(n)  asm volatile("cp.async.wait_group %0;" :: "n"(n) : "memory")

#define LDSM_X4(r, a)                                                        \
    asm volatile("ldmatrix.sync.aligned.m8n8.x4.shared.b16 {%0,%1,%2,%3}, [%4];" \
        : "=r"((r)[0]), "=r"((r)[1]), "=r"((r)[2]), "=r"((r)[3]) : "r"(a))
#define LDSM_X2(r, a)                                                        \
    asm volatile("ldmatrix.sync.aligned.m8n8.x2.shared.b16 {%0,%1}, [%2];"   \
        : "=r"((r)[0]), "=r"((r)[1]) : "r"(a))

#define MMA_F16(d, a, b)                                                     \
    asm volatile("mma.sync.aligned.m16n8k16.row.col.f32.f16.f16.f32 "        \
        "{%0,%1,%2,%3}, {%4,%5,%6,%7}, {%8,%9}, {%0,%1,%2,%3};"              \
        : "+f"((d)[0]), "+f"((d)[1]), "+f"((d)[2]), "+f"((d)[3])             \
        : "r"((a)[0]), "r"((a)[1]), "r"((a)[2]), "r"((a)[3]),                \
          "r"((b)[0]), "r"((b)[1]))

/* ---------------- f32 -> f16 conversion pre-pass ---------------- */
__device__ __forceinline__ void cvt_loop(const float4* __restrict__ in,
                                         uint4* __restrict__ out, int n8)
{
    for (int i = blockIdx.x * blockDim.x + threadIdx.x; i < n8;
         i += gridDim.x * blockDim.x) {
        float4 a = in[2 * i], b = in[2 * i + 1];
        __half2 h0 = __floats2half2_rn(a.x, a.y);
        __half2 h1 = __floats2half2_rn(a.z, a.w);
        __half2 h2 = __floats2half2_rn(b.x, b.y);
        __half2 h3 = __floats2half2_rn(b.z, b.w);
        out[i] = make_uint4(*(uint32_t*)&h0, *(uint32_t*)&h1,
                            *(uint32_t*)&h2, *(uint32_t*)&h3);
    }
}
__global__ void __launch_bounds__(256) cvt_f16_kernel(
    const float4* __restrict__ in, uint4* __restrict__ out, int n8)
{
    cvt_loop(in, out, n8);
}
__global__ void __launch_bounds__(256) cvt_w4_kernel(
    const float4* w0, const float4* w1, const float4* w2, const float4* w3,
    uint4* o0, uint4* o1, uint4* o2, uint4* o3, int n8)
{
    const float4* in; uint4* out;
    switch (blockIdx.y) {
        case 0:  in = w0; out = o0; break;
        case 1:  in = w1; out = o1; break;
        case 2:  in = w2; out = o2; break;
        default: in = w3; out = o3; break;
    }
    cvt_loop(in, out, n8);
}
__global__ void __launch_bounds__(256) cvt_qv_kernel(
    const float4* a0, const float4* a1, uint4* o0, uint4* o1, int n8)
{
    cvt_loop(blockIdx.y ? a1 : a0, blockIdx.y ? o1 : o0, n8);
}
__global__ void __launch_bounds__(256) cvt_mem_kernel(
    const float* __restrict__ mem, __half* __restrict__ mk,
    __half* __restrict__ mv, int n)
{
    for (int i = blockIdx.x * blockDim.x + threadIdx.x; i < n;
         i += gridDim.x * blockDim.x) {
        float m = mem[i];
        mk[i] = __float2half(m * SQRT_D_C);
        mv[i] = __float2half(m * SQRT_MEM_C);
    }
}

/* =========================================================================
 * proj_h: C = groupnorm(celu(A @ W^T + bias)), fp16 mma.sync m16n8k16.
 * CTA tile 128(M) x 128(N), BK=64, 8 warps (2x4) of 64x32 warp tiles.
 * 3-stage cp.async pipeline; smem 110592 B -> 2 CTAs/SM (bubble hiding).
 * Groupnorm group (D=128) == CTA N-tile. Epilogue consts overlay stage 0.
 * grid = (8, rows/128), 256 threads.
 * ========================================================================= */
#define RSTR    144                      /* 64 halves + 16B pad            */
#define STAGE_B (256 * RSTR)             /* 128 A rows + 128 W rows: 36864 */
#define PROJ_SMEM (3 * STAGE_B)          /* 110592 bytes                   */

__device__ __forceinline__ void proj_issue(
    uint32_t stage, const __half* __restrict__ hA,
    const __half* __restrict__ hW, size_t rowBase, size_t colBase,
    int ch, int tid)
{
#pragma unroll
    for (int i = 0; i < 4; i++) {
        int idx = tid + 256 * i;         /* 0..1023 : 128 rows x 8 cp16 */
        int r = idx >> 3, c = idx & 7;
        cp16(stage + r * RSTR + c * 16,
             hA + (rowBase + r) * 1024 + ch * 64 + c * 8);
        cp16(stage + (128 + r) * RSTR + c * 16,
             hW + (colBase + r) * 1024 + ch * 64 + c * 8);
    }
}

template <typename OT>
__global__ void __launch_bounds__(256, 2) proj_h(
    const __half* __restrict__ hA, const __half* __restrict__ hW,
    const float* __restrict__ bias, const float* __restrict__ gamma,
    const float* __restrict__ beta, OT* __restrict__ C)
{
    extern __shared__ char smem[];
    const uint32_t sb = smem_u32(smem);

    const int tid  = threadIdx.x;
    const int lane = tid & 31;
    const int wid  = tid >> 5;
    const int wm   = wid >> 2;           /* 0..1 : 64-row slab */
    const int wn   = wid & 3;            /* 0..3 : 32-col slab */
    const int g    = lane >> 2;
    const int tc   = lane & 3;

    const size_t rowBase = (size_t)blockIdx.y * 128;
    const size_t colBase = (size_t)blockIdx.x * 128;

    float acc[4][4][4];
#pragma unroll
    for (int mt = 0; mt < 4; mt++)
#pragma unroll
        for (int nt = 0; nt < 4; nt++)
#pragma unroll
            for (int z = 0; z < 4; z++) acc[mt][nt][z] = 0.f;

    proj_issue(sb + 0 * STAGE_B, hA, hW, rowBase, colBase, 0, tid); CP_COMMIT();
    proj_issue(sb + 1 * STAGE_B, hA, hW, rowBase, colBase, 1, tid); CP_COMMIT();

    const uint32_t aAddrBase = (uint32_t)((wm * 64 + (lane & 15)) * RSTR + (lane >> 4) * 16);
    const uint32_t bAddrBase = (uint32_t)((128 + wn * 32 + (lane & 7)) * RSTR + ((lane >> 3) & 1) * 16);

    int slot = 0;
    for (int ch = 0; ch < 16; ch++) {
        CP_WAIT(1);
        __syncthreads();
        if (ch + 2 < 16) {
            int ns = slot + 2; if (ns >= 3) ns -= 3;
            proj_issue(sb + ns * STAGE_B, hA, hW, rowBase, colBase, ch + 2, tid);
        }
        CP_COMMIT();

        const uint32_t S = sb + slot * STAGE_B;
        if (++slot == 3) slot = 0;
#pragma unroll
        for (int ks = 0; ks < 4; ks++) {
            uint32_t af[4][4], bf[4][2];
#pragma unroll
            for (int mt = 0; mt < 4; mt++)
                LDSM_X4(af[mt], S + aAddrBase + mt * 16 * RSTR + ks * 32);
#pragma unroll
            for (int nt = 0; nt < 4; nt++)
                LDSM_X2(bf[nt], S + bAddrBase + nt * 8 * RSTR + ks * 32);
#pragma unroll
            for (int mt = 0; mt < 4; mt++)
#pragma unroll
                for (int nt = 0; nt < 4; nt++)
                    MMA_F16(acc[mt][nt], af[mt], bf[nt]);
        }
    }
    CP_WAIT(0);
    __syncthreads();

    /* ------- epilogue: bias + celu + groupnorm (overlay stage-0 smem) ---- */
    float* SB = (float*)smem;            /* 128 f32 */
    float* SG = SB + 128;
    float* SE = SG + 128;
    float* RS = SE + 128;                /* [128][4] */
    float* RQ = RS + 512;                /* [128][4] */

    if (tid < 128) {
        SB[tid] = bias [colBase + tid];
        SG[tid] = gamma[colBase + tid];
        SE[tid] = beta [colBase + tid];
    }
    __syncthreads();

#pragma unroll
    for (int mt = 0; mt < 4; mt++)
#pragma unroll
        for (int half = 0; half < 2; half++) {
            const int r = wm * 64 + mt * 16 + half * 8 + g;
            float s = 0.f, q = 0.f;
#pragma unroll
            for (int nt = 0; nt < 4; nt++) {
                const int c0 = wn * 32 + nt * 8 + 2 * tc;
                float x0 = acc[mt][nt][half * 2 + 0] + SB[c0];
                float x1 = acc[mt][nt][half * 2 + 1] + SB[c0 + 1];
                x0 = (x0 > 0.f) ? x0 : ALPHA_C * expm1f(x0 * (1.0f / ALPHA_C));
                x1 = (x1 > 0.f) ? x1 : ALPHA_C * expm1f(x1 * (1.0f / ALPHA_C));
                acc[mt][nt][half * 2 + 0] = x0;
                acc[mt][nt][half * 2 + 1] = x1;
                s += x0 + x1; q += x0 * x0 + x1 * x1;
            }
            s += __shfl_xor_sync(0xffffffffu, s, 1);
            s += __shfl_xor_sync(0xffffffffu, s, 2);
            q += __shfl_xor_sync(0xffffffffu, q, 1);
            q += __shfl_xor_sync(0xffffffffu, q, 2);
            if (tc == 0) { RS[r * 4 + wn] = s; RQ[r * 4 + wn] = q; }
        }
    __syncthreads();

#pragma unroll
    for (int mt = 0; mt < 4; mt++)
#pragma unroll
        for (int half = 0; half < 2; half++) {
            const int r = wm * 64 + mt * 16 + half * 8 + g;
            const float S = RS[r * 4 + 0] + RS[r * 4 + 1]
                          + RS[r * 4 + 2] + RS[r * 4 + 3];
            const float Q = RQ[r * 4 + 0] + RQ[r * 4 + 1]
                          + RQ[r * 4 + 2] + RQ[r * 4 + 3];
            const float mean = S * (1.f / 128.f);
            const float var  = Q * (1.f / 128.f) - mean * mean;
            const float inv  = rsqrtf(var + EPS_C);
            OT* Crow = C + (rowBase + r) * 1024 + colBase;
#pragma unroll
            for (int nt = 0; nt < 4; nt++) {
                const int c0 = wn * 32 + nt * 8 + 2 * tc;
                float ox = (acc[mt][nt][half * 2 + 0] - mean) * inv * SG[c0]     + SE[c0];
                float oy = (acc[mt][nt][half * 2 + 1] - mean) * inv * SG[c0 + 1] + SE[c0 + 1];
                if constexpr (sizeof(OT) == 4) {
                    *(float2*)&Crow[c0] = make_float2(ox, oy);
                } else {
                    *(__half2*)&Crow[c0] = __floats2half2_rn(ox, oy);
                }
            }
        }
}

/* =========================================================================
 * attn_mma: per (b,h) block.
 * Fold q into Wb:  Wq'[o,d] = Wb[o,d] * q[b,h,d]  (f16)
 * h[m,o] = relu(K[m,:] . Wq'[o,:] + bb[o])   via fp16 mma.sync.
 * Emits masked logits (h.Wl + bl) and masked mean pool.
 * ========================================================================= */
#define ASTR      272                     /* 128 halfs + 16B pad            */
#define KSTAGE_B  (128 * ASTR)
#define ATTN_SMEM (64 * ASTR + 3 * KSTAGE_B + 8 * 64 * 4 + 16)

__device__ __forceinline__ void attn_issue(uint32_t stage, int mbase,
                                           int b, int h, int tid)
{
#pragma unroll
    for (int i = 0; i < 8; i++) {
        int c = tid + 256 * i;           /* 0..2047 */
        int r = c >> 4, col = c & 15;
        int mg = mbase + r;
        const __half* src;
        if (mg < Mseq) {
            src = g_hKout + ((size_t)(b * Mseq + mg)) * 1024 + h * 128 + col * 8;
        } else {
            int mm = mg - Mseq;
            if (mm >= MEMN) mm = 0;      /* OOB rows: garbage, masked later */
            src = g_hMemK + (size_t)mm * 1024 + h * 128 + col * 8;
        }
        cp16(stage + r * ASTR + col * 16, src);
    }
}

__global__ void __launch_bounds__(256, 1) attn_mma(
    const float* __restrict__ mask, const float* __restrict__ Wb,
    const float* __restrict__ bb, const float* __restrict__ Wl,
    const float* __restrict__ bl)
{
    extern __shared__ char sm[];
    const uint32_t sb = smem_u32(sm);
    const uint32_t WQ = sb;
    const uint32_t KT = sb + 64 * ASTR;
    float* PR  = (float*)(sm + 64 * ASTR + 3 * KSTAGE_B);
    float* MSM = PR + 8 * 64;

    const int bh = blockIdx.x, b = bh >> 3, h = bh & 7;
    const int tid = threadIdx.x;
    const int lane = tid & 31;
    const int wid  = tid >> 5;
    const int g    = lane >> 2;
    const int tc   = lane & 3;

    /* Wq'[o][d] = Wb[o][d] * q[d], f16 into smem */
    const float* qrow = g_q + (size_t)b * 1024 + h * 128;
    for (int idx = tid; idx < 8192; idx += 256) {
        int o = idx >> 7, d = idx & 127;
        float w = Wb[o * 128 + d] * qrow[d];
        *(__half*)(sm + o * ASTR + d * 2) = __float2half(w);
    }
    if (tid < 32) {
        float s = 0.f;
        for (int m = tid; m < MFULL; m += 32) {
            int mm = (m < Mseq) ? m : (m - Mseq);
            s += mask[b * Mseq + mm];
        }
#pragma unroll
        for (int o = 16; o; o >>= 1) s += __shfl_xor_sync(0xffffffffu, s, o);
        if (tid == 0) MSM[0] = s;
    }

    attn_issue(KT + 0 * KSTAGE_B,   0, b, h, tid); CP_COMMIT();
    attn_issue(KT + 1 * KSTAGE_B, 128, b, h, tid); CP_COMMIT();

    float bbf[8][2], wlf[8][2];
#pragma unroll
    for (int nt = 0; nt < 8; nt++) {
        const int c0 = nt * 8 + 2 * tc;
        bbf[nt][0] = bb[c0]; bbf[nt][1] = bb[c0 + 1];
        wlf[nt][0] = Wl[c0]; wlf[nt][1] = Wl[c0 + 1];
    }
    const float bl0 = bl[0];
    const float* maskb = mask + (size_t)b * Mseq;

    float pool[8][2];
#pragma unroll
    for (int nt = 0; nt < 8; nt++) { pool[nt][0] = 0.f; pool[nt][1] = 0.f; }

    const uint32_t aBase = (uint32_t)((wid * 16 + (lane & 15)) * ASTR + (lane >> 4) * 16);
    const uint32_t bBase = (uint32_t)((lane & 7) * ASTR + ((lane >> 3) & 1) * 16);

    for (int it = 0; it < 9; it++) {
        CP_WAIT(1);
        __syncthreads();
        if (it + 2 < 9) {
            attn_issue(KT + ((it + 2) % 3) * KSTAGE_B, (it + 2) * 128, b, h, tid);
            CP_COMMIT();
        }
        const uint32_t S = KT + (it % 3) * KSTAGE_B;

        float acc[8][4];
#pragma unroll
        for (int nt = 0; nt < 8; nt++)
#pragma unroll
            for (int z = 0; z < 4; z++) acc[nt][z] = 0.f;

#pragma unroll
        for (int ks = 0; ks < 8; ks++) {
            uint32_t af[4];
            LDSM_X4(af, S + aBase + ks * 32);
#pragma unroll
            for (int nt = 0; nt < 8; nt++) {
                uint32_t bf[2];
                LDSM_X2(bf, WQ + bBase + nt * 8 * ASTR + ks * 32);
                MMA_F16(acc[nt], af, bf);
            }
        }

        /* epilogue: relu + logits + pool */
        const int mg0 = it * 128 + wid * 16 + g;
        const int mg1 = mg0 + 8;
        float mv0 = 0.f, mv1 = 0.f;
        if (mg0 < MFULL) mv0 = maskb[(mg0 < Mseq) ? mg0 : (mg0 - Mseq)];
        if (mg1 < MFULL) mv1 = maskb[(mg1 < Mseq) ? mg1 : (mg1 - Mseq)];

        float s0 = 0.f, s1 = 0.f;
#pragma unroll
        for (int nt = 0; nt < 8; nt++) {
            float h00 = fmaxf(acc[nt][0] + bbf[nt][0], 0.f);
            float h01 = fmaxf(acc[nt][1] + bbf[nt][1], 0.f);
            float h10 = fmaxf(acc[nt][2] + bbf[nt][0], 0.f);
            float h11 = fmaxf(acc[nt][3] + bbf[nt][1], 0.f);
            s0 += h00 * wlf[nt][0] + h01 * wlf[nt][1];
            s1 += h10 * wlf[nt][0] + h11 * wlf[nt][1];
            pool[nt][0] += h00 * mv0 + h10 * mv1;
            pool[nt][1] += h01 * mv0 + h11 * mv1;
        }
        s0 += __shfl_xor_sync(0xffffffffu, s0, 1);
        s0 += __shfl_xor_sync(0xffffffffu, s0, 2);
        s1 += __shfl_xor_sync(0xffffffffu, s1, 1);
        s1 += __shfl_xor_sync(0xffffffffu, s1, 2);
        if (tc == 0) {
            if (mg0 < MFULL)
                g_logits[(size_t)bh * MFULL + mg0] = (mv0 == 0.f) ? -1e9f : s0 + bl0;
            if (mg1 < MFULL)
                g_logits[(size_t)bh * MFULL + mg1] = (mv1 == 0.f) ? -1e9f : s1 + bl0;
        }
    }

    /* pool reduction */
#pragma unroll
    for (int nt = 0; nt < 8; nt++)
#pragma unroll
        for (int c = 0; c < 2; c++) {
            float v = pool[nt][c];
            v += __shfl_xor_sync(0xffffffffu, v, 4);
            v += __shfl_xor_sync(0xffffffffu, v, 8);
            v += __shfl_xor_sync(0xffffffffu, v, 16);
            if (lane < 4) PR[wid * 64 + nt * 8 + 2 * lane + c] = v;
        }
    __syncthreads();
    if (tid < 64) {
        float s = 0.f;
#pragma unroll
        for (int w = 0; w < 8; w++) s += PR[w * 64 + tid];
        g_pool[(size_t)bh * 64 + tid] = s / MSM[0];
    }
}

/* =========================================================================
 * finalize: softmax(logits), alpha_channel = sigmoid(pool@Wl2^T+bl2),
 * v2p = sum_m alpha * v2,  out = v1 * v2p * alpha_channel
 * ========================================================================= */
__global__ void __launch_bounds__(256) finalize_kernel(
    const float* __restrict__ Wl2, const float* __restrict__ bl2,
    float* __restrict__ out)
{
    __shared__ float alpha[MFULL];
    __shared__ float red[256];
    __shared__ float pool_s[64];
    __shared__ float vpart[256];

    const int bh = blockIdx.x, b = bh >> 3, h = bh & 7;
    const int tid = threadIdx.x;

    float mx = -INFINITY;
    for (int m = tid; m < MFULL; m += 256) {
        float l = g_logits[(size_t)bh * MFULL + m];
        alpha[m] = l;
        mx = fmaxf(mx, l);
    }
    red[tid] = mx;
    __syncthreads();
    for (int s = 128; s > 0; s >>= 1) {
        if (tid < s) red[tid] = fmaxf(red[tid], red[tid + s]);
        __syncthreads();
    }
    mx = red[0];
    __syncthreads();

    float es = 0.f;
    for (int m = tid; m < MFULL; m += 256) {
        float e = expf(alpha[m] - mx);
        alpha[m] = e;
        es += e;
    }
    red[tid] = es;
    if (tid < 64) pool_s[tid] = g_pool[(size_t)bh * 64 + tid];
    __syncthreads();
    for (int s = 128; s > 0; s >>= 1) {
        if (tid < s) red[tid] += red[tid + s];
        __syncthreads();
    }
    const float sumExp = red[0];

    const int d = tid & 127, half = tid >> 7;
    float acc = 0.f;
    for (int m = half; m < MFULL; m += 2) {
        float a = alpha[m];
        float v;
        if (m < Mseq)
            v = __half2float(g_hV2out[((size_t)(b * Mseq + m)) * 1024 + h * 128 + d]);
        else
            v = __half2float(g_hMemV[(size_t)(m - Mseq) * 1024 + h * 128 + d]);
        acc += a * v;
    }
    vpart[tid] = acc;
    __syncthreads();

    if (tid < 128) {
        float v2p = (vpart[tid] + vpart[tid + 128]) / sumExp;
        float s = bl2[d];
#pragma unroll
        for (int o = 0; o < 64; o++) s += pool_s[o] * Wl2[d * 64 + o];
        float ac = 1.f / (1.f + expf(-s));
        size_t oidx = (size_t)b * Ee + h * Dd + d;
        out[oidx] = g_v1[oidx] * v2p * ac;
    }
}

/* ========================================================================= */
extern "C" void kernel_launch(void* const* d_in, const int* in_sizes, int n_in,
                              void* d_out, int out_size)
{
    const float* query  = (const float*)d_in[0];
    const float* key    = (const float*)d_in[1];
    const float* mask   = (const float*)d_in[2];
    const float* value1 = (const float*)d_in[3];
    const float* value2 = (const float*)d_in[4];
    const float* Wq  = (const float*)d_in[5];  const float* bq  = (const float*)d_in[6];
    const float* gq  = (const float*)d_in[7];  const float* sq  = (const float*)d_in[8];
    const float* Wk  = (const float*)d_in[9];  const float* bk  = (const float*)d_in[10];
    const float* gk  = (const float*)d_in[11]; const float* sk  = (const float*)d_in[12];
    const float* Wv1 = (const float*)d_in[13]; const float* bv1 = (const float*)d_in[14];
    const float* gv1 = (const float*)d_in[15]; const float* sv1 = (const float*)d_in[16];
    const float* Wv2 = (const float*)d_in[17]; const float* bv2 = (const float*)d_in[18];
    const float* gv2 = (const float*)d_in[19]; const float* sv2 = (const float*)d_in[20];
    const float* mem = (const float*)d_in[21];
    const float* Wb  = (const float*)d_in[22]; const float* bb  = (const float*)d_in[23];
    const float* Wl  = (const float*)d_in[24]; const float* bl  = (const float*)d_in[25];
    const float* Wl2 = (const float*)d_in[26]; const float* bl2 = (const float*)d_in[27];
    float* out = (float*)d_out;

    void *pq, *pv1;
    cudaGetSymbolAddress(&pq,  g_q);
    cudaGetSymbolAddress(&pv1, g_v1);
    void *phKey, *phV2in, *phKout, *phV2out, *phQ, *phV1;
    void *phWq, *phWk, *phWv1, *phWv2, *phMemK, *phMemV;
    cudaGetSymbolAddress(&phKey,  g_hKey);
    cudaGetSymbolAddress(&phV2in, g_hV2in);
    cudaGetSymbolAddress(&phKout, g_hKout);
    cudaGetSymbolAddress(&phV2out,g_hV2out);
    cudaGetSymbolAddress(&phQ,    g_hQin);
    cudaGetSymbolAddress(&phV1,   g_hV1in);
    cudaGetSymbolAddress(&phWq,   g_hWq);
    cudaGetSymbolAddress(&phWk,   g_hWk);
    cudaGetSymbolAddress(&phWv1,  g_hWv1);
    cudaGetSymbolAddress(&phWv2,  g_hWv2);
    cudaGetSymbolAddress(&phMemK, g_hMemK);
    cudaGetSymbolAddress(&phMemV, g_hMemV);

    cudaFuncSetAttribute(proj_h<float>,
                         cudaFuncAttributeMaxDynamicSharedMemorySize, PROJ_SMEM);
    cudaFuncSetAttribute(proj_h<__half>,
                         cudaFuncAttributeMaxDynamicSharedMemorySize, PROJ_SMEM);
    cudaFuncSetAttribute(attn_mma,
                         cudaFuncAttributeMaxDynamicSharedMemorySize, ATTN_SMEM);

    const int BIGN8 = (int)(((size_t)Bq * Mseq * Ee) / 8);

    /* launch 0: all four weight conversions */
    cvt_w4_kernel<<<dim3(512, 4), 256>>>(
        (const float4*)Wq, (const float4*)Wk, (const float4*)Wv1, (const float4*)Wv2,
        (uint4*)phWq, (uint4*)phWk, (uint4*)phWv1, (uint4*)phWv2, Ee * Ee / 8);
    /* launch 1: key f32->f16 */
    cvt_f16_kernel<<<4096, 256>>>((const float4*)key, (uint4*)phKey, BIGN8);
    /* launch 2: value2 f32->f16 */
    cvt_f16_kernel<<<4096, 256>>>((const float4*)value2, (uint4*)phV2in, BIGN8);
    /* launch 3: K projection  <-- ncu-profiled slot (index 3) */
    proj_h<__half><<<dim3(8, 1024), 256, PROJ_SMEM>>>(
        (const __half*)phKey, (const __half*)phWk, bk, gk, sk, (__half*)phKout);
    /* launch 4: V2 projection */
    proj_h<__half><<<dim3(8, 1024), 256, PROJ_SMEM>>>(
        (const __half*)phV2in, (const __half*)phWv2, bv2, gv2, sv2, (__half*)phV2out);
    /* launch 5: query+value1 conversion */
    cvt_qv_kernel<<<dim3(128, 2), 256>>>(
        (const float4*)query, (const float4*)value1,
        (uint4*)phQ, (uint4*)phV1, Bq * Ee / 8);
    /* launch 6: mem scaling */
    cvt_mem_kernel<<<40, 256>>>(mem, (__half*)phMemK, (__half*)phMemV, MEMN * Ee);
    /* launches 7,8: small projections */
    proj_h<float><<<dim3(8, 1), 256, PROJ_SMEM>>>(
        (const __half*)phQ,  (const __half*)phWq,  bq,  gq,  sq,  (float*)pq);
    proj_h<float><<<dim3(8, 1), 256, PROJ_SMEM>>>(
        (const __half*)phV1, (const __half*)phWv1, bv1, gv1, sv1, (float*)pv1);
    /* launch 9: low-rank scoring */
    attn_mma<<<Bq * Hh, 256, ATTN_SMEM>>>(mask, Wb, bb, Wl, bl);
    /* launch 10: softmax + gate + weighted sum */
    finalize_kernel<<<Bq * Hh, 256>>>(Wl2, bl2, out);
}

// round 10
// speedup vs baseline: 5.9743x; 1.0226x over previous
#include <cuda_runtime.h>
#include <cuda_fp16.h>
#include <math.h>
#include <stdint.h>

#define Bq    128
#define Mseq  1024
#define Ee    1024
#define Hh    8
#define Dd    128
#define MEMN  40
#define MFULL 1064
#define MIDN  64
#define ALPHA_C 1.3f
#define EPS_C   1e-5f
#define SQRT_D_C    11.313708498984760390f   /* sqrt(128) */
#define SQRT_MEM_C  6.3245553203367586640f   /* sqrt(40)  */

/* ---------------- scratch (static device memory: allowed) ---------------- */
__device__ float  g_q   [Bq * Ee];
__device__ float  g_v1  [Bq * Ee];
__device__ float  g_pool[Bq * Hh * MIDN];
__device__ float  g_logits[Bq * Hh * MFULL];

__device__ __half g_hKey [(size_t)Bq * Mseq * Ee];
__device__ __half g_hV2in[(size_t)Bq * Mseq * Ee];
__device__ __half g_hKout[(size_t)Bq * Mseq * Ee];
__device__ __half g_hV2out[(size_t)Bq * Mseq * Ee];
__device__ __half g_hQin [Bq * Ee];
__device__ __half g_hV1in[Bq * Ee];
__device__ __half g_hWq [Ee * Ee];
__device__ __half g_hWk [Ee * Ee];
__device__ __half g_hWv1[Ee * Ee];
__device__ __half g_hWv2[Ee * Ee];
__device__ __half g_hMemK[MEMN * Ee];
__device__ __half g_hMemV[MEMN * Ee];

/* ======================= helpers =========================== */
__device__ __forceinline__ uint32_t smem_u32(const void* p) {
    uint32_t a;
    asm("{ .reg .u64 t; cvta.to.shared.u64 t, %1; cvt.u32.u64 %0, t; }"
        : "=r"(a) : "l"(p));
    return a;
}
__device__ __forceinline__ void cp16(uint32_t s, const void* g) {
    asm volatile("cp.async.ca.shared.global [%0], [%1], 16;"
                 :: "r"(s), "l"(g) : "memory");
}
#define CP_COMMIT() asm volatile("cp.async.commit_group;" ::: "memory")
#define CP_WAIT(n)  asm volatile("cp.async.wait_group %0;" :: "n"(n) : "memory")

#define LDSM_X4(r, a)                                                        \
    asm volatile("ldmatrix.sync.aligned.m8n8.x4.shared.b16 {%0,%1,%2,%3}, [%4];" \
        : "=r"((r)[0]), "=r"((r)[1]), "=r"((r)[2]), "=r"((r)[3]) : "r"(a))
#define LDSM_X2(r, a)                                                        \
    asm volatile("ldmatrix.sync.aligned.m8n8.x2.shared.b16 {%0,%1}, [%2];"   \
        : "=r"((r)[0]), "=r"((r)[1]) : "r"(a))

#define MMA_F16(d, a, b)                                                     \
    asm volatile("mma.sync.aligned.m16n8k16.row.col.f32.f16.f16.f32 "        \
        "{%0,%1,%2,%3}, {%4,%5,%6,%7}, {%8,%9}, {%0,%1,%2,%3};"              \
        : "+f"((d)[0]), "+f"((d)[1]), "+f"((d)[2]), "+f"((d)[3])             \
        : "r"((a)[0]), "r"((a)[1]), "r"((a)[2]), "r"((a)[3]),                \
          "r"((b)[0]), "r"((b)[1]))

/* ---------------- f32 -> f16 conversion pre-pass ---------------- */
__device__ __forceinline__ void cvt_loop(const float4* __restrict__ in,
                                         uint4* __restrict__ out, int n8)
{
    for (int i = blockIdx.x * blockDim.x + threadIdx.x; i < n8;
         i += gridDim.x * blockDim.x) {
        float4 a = in[2 * i], b = in[2 * i + 1];
        __half2 h0 = __floats2half2_rn(a.x, a.y);
        __half2 h1 = __floats2half2_rn(a.z, a.w);
        __half2 h2 = __floats2half2_rn(b.x, b.y);
        __half2 h3 = __floats2half2_rn(b.z, b.w);
        out[i] = make_uint4(*(uint32_t*)&h0, *(uint32_t*)&h1,
                            *(uint32_t*)&h2, *(uint32_t*)&h3);
    }
}
__global__ void __launch_bounds__(256) cvt_f16_kernel(
    const float4* __restrict__ in, uint4* __restrict__ out, int n8)
{
    cvt_loop(in, out, n8);
}
__global__ void __launch_bounds__(256) cvt_w4_kernel(
    const float4* w0, const float4* w1, const float4* w2, const float4* w3,
    uint4* o0, uint4* o1, uint4* o2, uint4* o3, int n8)
{
    const float4* in; uint4* out;
    switch (blockIdx.y) {
        case 0:  in = w0; out = o0; break;
        case 1:  in = w1; out = o1; break;
        case 2:  in = w2; out = o2; break;
        default: in = w3; out = o3; break;
    }
    cvt_loop(in, out, n8);
}
__global__ void __launch_bounds__(256) cvt_qv_kernel(
    const float4* a0, const float4* a1, uint4* o0, uint4* o1, int n8)
{
    cvt_loop(blockIdx.y ? a1 : a0, blockIdx.y ? o1 : o0, n8);
}
__global__ void __launch_bounds__(256) cvt_mem_kernel(
    const float* __restrict__ mem, __half* __restrict__ mk,
    __half* __restrict__ mv, int n)
{
    for (int i = blockIdx.x * blockDim.x + threadIdx.x; i < n;
         i += gridDim.x * blockDim.x) {
        float m = mem[i];
        mk[i] = __float2half(m * SQRT_D_C);
        mv[i] = __float2half(m * SQRT_MEM_C);
    }
}

/* =========================================================================
 * proj_h: C = groupnorm(celu(A @ W^T + bias)), fp16 mma.sync m16n8k16.
 * CTA tile 128x128, BK=64, 8 warps (2x4), 3-stage cp.async, 2 CTAs/SM.
 * B fragments via ldmatrix.x4 (2 nt tiles + both k-halves per instr).
 * ========================================================================= */
#define RSTR    144
#define STAGE_B (256 * RSTR)
#define PROJ_SMEM (3 * STAGE_B)          /* 110592 bytes */

__device__ __forceinline__ void proj_issue(
    uint32_t stage, const __half* __restrict__ hA,
    const __half* __restrict__ hW, size_t rowBase, size_t colBase,
    int ch, int tid)
{
#pragma unroll
    for (int i = 0; i < 4; i++) {
        int idx = tid + 256 * i;
        int r = idx >> 3, c = idx & 7;
        cp16(stage + r * RSTR + c * 16,
             hA + (rowBase + r) * 1024 + ch * 64 + c * 8);
        cp16(stage + (128 + r) * RSTR + c * 16,
             hW + (colBase + r) * 1024 + ch * 64 + c * 8);
    }
}

template <typename OT>
__global__ void __launch_bounds__(256, 2) proj_h(
    const __half* __restrict__ hA, const __half* __restrict__ hW,
    const float* __restrict__ bias, const float* __restrict__ gamma,
    const float* __restrict__ beta, OT* __restrict__ C)
{
    extern __shared__ char smem[];
    const uint32_t sb = smem_u32(smem);

    const int tid  = threadIdx.x;
    const int lane = tid & 31;
    const int wid  = tid >> 5;
    const int wm   = wid >> 2;
    const int wn   = wid & 3;
    const int g    = lane >> 2;
    const int tc   = lane & 3;

    const size_t rowBase = (size_t)blockIdx.y * 128;
    const size_t colBase = (size_t)blockIdx.x * 128;

    float acc[4][4][4];
#pragma unroll
    for (int mt = 0; mt < 4; mt++)
#pragma unroll
        for (int nt = 0; nt < 4; nt++)
#pragma unroll
            for (int z = 0; z < 4; z++) acc[mt][nt][z] = 0.f;

    proj_issue(sb + 0 * STAGE_B, hA, hW, rowBase, colBase, 0, tid); CP_COMMIT();
    proj_issue(sb + 1 * STAGE_B, hA, hW, rowBase, colBase, 1, tid); CP_COMMIT();

    const uint32_t aAddrBase =
        (uint32_t)((wm * 64 + (lane & 15)) * RSTR + (lane >> 4) * 16);
    /* B x4: lanes 0-7 -> nt0/kk0, 8-15 -> nt0/kk1, 16-23 -> nt1/kk0,
       24-31 -> nt1/kk1 */
    const uint32_t bAddrBase =
        (uint32_t)((128 + wn * 32 + ((lane >> 4) & 1) * 8 + (lane & 7)) * RSTR
                   + ((lane >> 3) & 1) * 16);

    int slot = 0;
    for (int ch = 0; ch < 16; ch++) {
        CP_WAIT(1);
        __syncthreads();
        if (ch + 2 < 16) {
            int ns = slot + 2; if (ns >= 3) ns -= 3;
            proj_issue(sb + ns * STAGE_B, hA, hW, rowBase, colBase, ch + 2, tid);
        }
        CP_COMMIT();

        const uint32_t S = sb + slot * STAGE_B;
        if (++slot == 3) slot = 0;
#pragma unroll
        for (int ks = 0; ks < 4; ks++) {
            uint32_t af[4][4], bf[4][2];
#pragma unroll
            for (int mt = 0; mt < 4; mt++)
                LDSM_X4(af[mt], S + aAddrBase + mt * 16 * RSTR + ks * 32);
#pragma unroll
            for (int j = 0; j < 2; j++) {
                uint32_t t[4];
                LDSM_X4(t, S + bAddrBase + j * 16 * RSTR + ks * 32);
                bf[2 * j][0] = t[0]; bf[2 * j][1] = t[1];
                bf[2 * j + 1][0] = t[2]; bf[2 * j + 1][1] = t[3];
            }
#pragma unroll
            for (int mt = 0; mt < 4; mt++)
#pragma unroll
                for (int nt = 0; nt < 4; nt++)
                    MMA_F16(acc[mt][nt], af[mt], bf[nt]);
        }
    }
    CP_WAIT(0);
    __syncthreads();

    /* ------- epilogue: bias + celu + groupnorm (overlay stage-0 smem) ---- */
    float* SB = (float*)smem;
    float* SG = SB + 128;
    float* SE = SG + 128;
    float* RS = SE + 128;
    float* RQ = RS + 512;

    if (tid < 128) {
        SB[tid] = bias [colBase + tid];
        SG[tid] = gamma[colBase + tid];
        SE[tid] = beta [colBase + tid];
    }
    __syncthreads();

#pragma unroll
    for (int mt = 0; mt < 4; mt++)
#pragma unroll
        for (int half = 0; half < 2; half++) {
            const int r = wm * 64 + mt * 16 + half * 8 + g;
            float s = 0.f, q = 0.f;
#pragma unroll
            for (int nt = 0; nt < 4; nt++) {
                const int c0 = wn * 32 + nt * 8 + 2 * tc;
                float x0 = acc[mt][nt][half * 2 + 0] + SB[c0];
                float x1 = acc[mt][nt][half * 2 + 1] + SB[c0 + 1];
                x0 = (x0 > 0.f) ? x0 : ALPHA_C * expm1f(x0 * (1.0f / ALPHA_C));
                x1 = (x1 > 0.f) ? x1 : ALPHA_C * expm1f(x1 * (1.0f / ALPHA_C));
                acc[mt][nt][half * 2 + 0] = x0;
                acc[mt][nt][half * 2 + 1] = x1;
                s += x0 + x1; q += x0 * x0 + x1 * x1;
            }
            s += __shfl_xor_sync(0xffffffffu, s, 1);
            s += __shfl_xor_sync(0xffffffffu, s, 2);
            q += __shfl_xor_sync(0xffffffffu, q, 1);
            q += __shfl_xor_sync(0xffffffffu, q, 2);
            if (tc == 0) { RS[r * 4 + wn] = s; RQ[r * 4 + wn] = q; }
        }
    __syncthreads();

#pragma unroll
    for (int mt = 0; mt < 4; mt++)
#pragma unroll
        for (int half = 0; half < 2; half++) {
            const int r = wm * 64 + mt * 16 + half * 8 + g;
            const float S = RS[r * 4 + 0] + RS[r * 4 + 1]
                          + RS[r * 4 + 2] + RS[r * 4 + 3];
            const float Q = RQ[r * 4 + 0] + RQ[r * 4 + 1]
                          + RQ[r * 4 + 2] + RQ[r * 4 + 3];
            const float mean = S * (1.f / 128.f);
            const float var  = Q * (1.f / 128.f) - mean * mean;
            const float inv  = rsqrtf(var + EPS_C);
            OT* Crow = C + (rowBase + r) * 1024 + colBase;
#pragma unroll
            for (int nt = 0; nt < 4; nt++) {
                const int c0 = wn * 32 + nt * 8 + 2 * tc;
                float ox = (acc[mt][nt][half * 2 + 0] - mean) * inv * SG[c0]     + SE[c0];
                float oy = (acc[mt][nt][half * 2 + 1] - mean) * inv * SG[c0 + 1] + SE[c0 + 1];
                if constexpr (sizeof(OT) == 4) {
                    *(float2*)&Crow[c0] = make_float2(ox, oy);
                } else {
                    *(__half2*)&Crow[c0] = __floats2half2_rn(ox, oy);
                }
            }
        }
}

/* =========================================================================
 * attn_mma: per (b,h) block; q folded into Wb; fp16 mma.sync scoring.
 * ========================================================================= */
#define ASTR      272
#define KSTAGE_B  (128 * ASTR)
#define ATTN_SMEM (64 * ASTR + 3 * KSTAGE_B + 8 * 64 * 4 + 16)

__device__ __forceinline__ void attn_issue(uint32_t stage, int mbase,
                                           int b, int h, int tid)
{
#pragma unroll
    for (int i = 0; i < 8; i++) {
        int c = tid + 256 * i;
        int r = c >> 4, col = c & 15;
        int mg = mbase + r;
        const __half* src;
        if (mg < Mseq) {
            src = g_hKout + ((size_t)(b * Mseq + mg)) * 1024 + h * 128 + col * 8;
        } else {
            int mm = mg - Mseq;
            if (mm >= MEMN) mm = 0;
            src = g_hMemK + (size_t)mm * 1024 + h * 128 + col * 8;
        }
        cp16(stage + r * ASTR + col * 16, src);
    }
}

__global__ void __launch_bounds__(256, 1) attn_mma(
    const float* __restrict__ mask, const float* __restrict__ Wb,
    const float* __restrict__ bb, const float* __restrict__ Wl,
    const float* __restrict__ bl)
{
    extern __shared__ char sm[];
    const uint32_t sb = smem_u32(sm);
    const uint32_t WQ = sb;
    const uint32_t KT = sb + 64 * ASTR;
    float* PR  = (float*)(sm + 64 * ASTR + 3 * KSTAGE_B);
    float* MSM = PR + 8 * 64;

    const int bh = blockIdx.x, b = bh >> 3, h = bh & 7;
    const int tid = threadIdx.x;
    const int lane = tid & 31;
    const int wid  = tid >> 5;
    const int g    = lane >> 2;
    const int tc   = lane & 3;

    const float* qrow = g_q + (size_t)b * 1024 + h * 128;
    for (int idx = tid; idx < 8192; idx += 256) {
        int o = idx >> 7, d = idx & 127;
        float w = Wb[o * 128 + d] * qrow[d];
        *(__half*)(sm + o * ASTR + d * 2) = __float2half(w);
    }
    if (tid < 32) {
        float s = 0.f;
        for (int m = tid; m < MFULL; m += 32) {
            int mm = (m < Mseq) ? m : (m - Mseq);
            s += mask[b * Mseq + mm];
        }
#pragma unroll
        for (int o = 16; o; o >>= 1) s += __shfl_xor_sync(0xffffffffu, s, o);
        if (tid == 0) MSM[0] = s;
    }

    attn_issue(KT + 0 * KSTAGE_B,   0, b, h, tid); CP_COMMIT();
    attn_issue(KT + 1 * KSTAGE_B, 128, b, h, tid); CP_COMMIT();

    float bbf[8][2], wlf[8][2];
#pragma unroll
    for (int nt = 0; nt < 8; nt++) {
        const int c0 = nt * 8 + 2 * tc;
        bbf[nt][0] = bb[c0]; bbf[nt][1] = bb[c0 + 1];
        wlf[nt][0] = Wl[c0]; wlf[nt][1] = Wl[c0 + 1];
    }
    const float bl0 = bl[0];
    const float* maskb = mask + (size_t)b * Mseq;

    float pool[8][2];
#pragma unroll
    for (int nt = 0; nt < 8; nt++) { pool[nt][0] = 0.f; pool[nt][1] = 0.f; }

    const uint32_t aBase = (uint32_t)((wid * 16 + (lane & 15)) * ASTR + (lane >> 4) * 16);
    const uint32_t bBase = (uint32_t)((lane & 7) * ASTR + ((lane >> 3) & 1) * 16);

    for (int it = 0; it < 9; it++) {
        CP_WAIT(1);
        __syncthreads();
        if (it + 2 < 9) {
            attn_issue(KT + ((it + 2) % 3) * KSTAGE_B, (it + 2) * 128, b, h, tid);
            CP_COMMIT();
        }
        const uint32_t S = KT + (it % 3) * KSTAGE_B;

        float acc[8][4];
#pragma unroll
        for (int nt = 0; nt < 8; nt++)
#pragma unroll
            for (int z = 0; z < 4; z++) acc[nt][z] = 0.f;

#pragma unroll
        for (int ks = 0; ks < 8; ks++) {
            uint32_t af[4];
            LDSM_X4(af, S + aBase + ks * 32);
#pragma unroll
            for (int nt = 0; nt < 8; nt++) {
                uint32_t bf[2];
                LDSM_X2(bf, WQ + bBase + nt * 8 * ASTR + ks * 32);
                MMA_F16(acc[nt], af, bf);
            }
        }

        const int mg0 = it * 128 + wid * 16 + g;
        const int mg1 = mg0 + 8;
        float mv0 = 0.f, mv1 = 0.f;
        if (mg0 < MFULL) mv0 = maskb[(mg0 < Mseq) ? mg0 : (mg0 - Mseq)];
        if (mg1 < MFULL) mv1 = maskb[(mg1 < Mseq) ? mg1 : (mg1 - Mseq)];

        float s0 = 0.f, s1 = 0.f;
#pragma unroll
        for (int nt = 0; nt < 8; nt++) {
            float h00 = fmaxf(acc[nt][0] + bbf[nt][0], 0.f);
            float h01 = fmaxf(acc[nt][1] + bbf[nt][1], 0.f);
            float h10 = fmaxf(acc[nt][2] + bbf[nt][0], 0.f);
            float h11 = fmaxf(acc[nt][3] + bbf[nt][1], 0.f);
            s0 += h00 * wlf[nt][0] + h01 * wlf[nt][1];
            s1 += h10 * wlf[nt][0] + h11 * wlf[nt][1];
            pool[nt][0] += h00 * mv0 + h10 * mv1;
            pool[nt][1] += h01 * mv0 + h11 * mv1;
        }
        s0 += __shfl_xor_sync(0xffffffffu, s0, 1);
        s0 += __shfl_xor_sync(0xffffffffu, s0, 2);
        s1 += __shfl_xor_sync(0xffffffffu, s1, 1);
        s1 += __shfl_xor_sync(0xffffffffu, s1, 2);
        if (tc == 0) {
            if (mg0 < MFULL)
                g_logits[(size_t)bh * MFULL + mg0] = (mv0 == 0.f) ? -1e9f : s0 + bl0;
            if (mg1 < MFULL)
                g_logits[(size_t)bh * MFULL + mg1] = (mv1 == 0.f) ? -1e9f : s1 + bl0;
        }
    }

#pragma unroll
    for (int nt = 0; nt < 8; nt++)
#pragma unroll
        for (int c = 0; c < 2; c++) {
            float v = pool[nt][c];
            v += __shfl_xor_sync(0xffffffffu, v, 4);
            v += __shfl_xor_sync(0xffffffffu, v, 8);
            v += __shfl_xor_sync(0xffffffffu, v, 16);
            if (lane < 4) PR[wid * 64 + nt * 8 + 2 * lane + c] = v;
        }
    __syncthreads();
    if (tid < 64) {
        float s = 0.f;
#pragma unroll
        for (int w = 0; w < 8; w++) s += PR[w * 64 + tid];
        g_pool[(size_t)bh * 64 + tid] = s / MSM[0];
    }
}

/* =========================================================================
 * finalize: softmax(logits), channel gate, weighted sum, output
 * ========================================================================= */
__global__ void __launch_bounds__(256) finalize_kernel(
    const float* __restrict__ Wl2, const float* __restrict__ bl2,
    float* __restrict__ out)
{
    __shared__ float alpha[MFULL];
    __shared__ float red[256];
    __shared__ float pool_s[64];
    __shared__ float vpart[256];

    const int bh = blockIdx.x, b = bh >> 3, h = bh & 7;
    const int tid = threadIdx.x;

    float mx = -INFINITY;
    for (int m = tid; m < MFULL; m += 256) {
        float l = g_logits[(size_t)bh * MFULL + m];
        alpha[m] = l;
        mx = fmaxf(mx, l);
    }
    red[tid] = mx;
    __syncthreads();
    for (int s = 128; s > 0; s >>= 1) {
        if (tid < s) red[tid] = fmaxf(red[tid], red[tid + s]);
        __syncthreads();
    }
    mx = red[0];
    __syncthreads();

    float es = 0.f;
    for (int m = tid; m < MFULL; m += 256) {
        float e = expf(alpha[m] - mx);
        alpha[m] = e;
        es += e;
    }
    red[tid] = es;
    if (tid < 64) pool_s[tid] = g_pool[(size_t)bh * 64 + tid];
    __syncthreads();
    for (int s = 128; s > 0; s >>= 1) {
        if (tid < s) red[tid] += red[tid + s];
        __syncthreads();
    }
    const float sumExp = red[0];

    const int d = tid & 127, half = tid >> 7;
    float acc = 0.f;
    for (int m = half; m < MFULL; m += 2) {
        float a = alpha[m];
        float v;
        if (m < Mseq)
            v = __half2float(g_hV2out[((size_t)(b * Mseq + m)) * 1024 + h * 128 + d]);
        else
            v = __half2float(g_hMemV[(size_t)(m - Mseq) * 1024 + h * 128 + d]);
        acc += a * v;
    }
    vpart[tid] = acc;
    __syncthreads();

    if (tid < 128) {
        float v2p = (vpart[tid] + vpart[tid + 128]) / sumExp;
        float s = bl2[d];
#pragma unroll
        for (int o = 0; o < 64; o++) s += pool_s[o] * Wl2[d * 64 + o];
        float ac = 1.f / (1.f + expf(-s));
        size_t oidx = (size_t)b * Ee + h * Dd + d;
        out[oidx] = g_v1[oidx] * v2p * ac;
    }
}

/* ========================================================================= */
extern "C" void kernel_launch(void* const* d_in, const int* in_sizes, int n_in,
                              void* d_out, int out_size)
{
    const float* query  = (const float*)d_in[0];
    const float* key    = (const float*)d_in[1];
    const float* mask   = (const float*)d_in[2];
    const float* value1 = (const float*)d_in[3];
    const float* value2 = (const float*)d_in[4];
    const float* Wq  = (const float*)d_in[5];  const float* bq  = (const float*)d_in[6];
    const float* gq  = (const float*)d_in[7];  const float* sq  = (const float*)d_in[8];
    const float* Wk  = (const float*)d_in[9];  const float* bk  = (const float*)d_in[10];
    const float* gk  = (const float*)d_in[11]; const float* sk  = (const float*)d_in[12];
    const float* Wv1 = (const float*)d_in[13]; const float* bv1 = (const float*)d_in[14];
    const float* gv1 = (const float*)d_in[15]; const float* sv1 = (const float*)d_in[16];
    const float* Wv2 = (const float*)d_in[17]; const float* bv2 = (const float*)d_in[18];
    const float* gv2 = (const float*)d_in[19]; const float* sv2 = (const float*)d_in[20];
    const float* mem = (const float*)d_in[21];
    const float* Wb  = (const float*)d_in[22]; const float* bb  = (const float*)d_in[23];
    const float* Wl  = (const float*)d_in[24]; const float* bl  = (const float*)d_in[25];
    const float* Wl2 = (const float*)d_in[26]; const float* bl2 = (const float*)d_in[27];
    float* out = (float*)d_out;

    void *pq, *pv1;
    cudaGetSymbolAddress(&pq,  g_q);
    cudaGetSymbolAddress(&pv1, g_v1);
    void *phKey, *phV2in, *phKout, *phV2out, *phQ, *phV1;
    void *phWq, *phWk, *phWv1, *phWv2, *phMemK, *phMemV;
    cudaGetSymbolAddress(&phKey,  g_hKey);
    cudaGetSymbolAddress(&phV2in, g_hV2in);
    cudaGetSymbolAddress(&phKout, g_hKout);
    cudaGetSymbolAddress(&phV2out,g_hV2out);
    cudaGetSymbolAddress(&phQ,    g_hQin);
    cudaGetSymbolAddress(&phV1,   g_hV1in);
    cudaGetSymbolAddress(&phWq,   g_hWq);
    cudaGetSymbolAddress(&phWk,   g_hWk);
    cudaGetSymbolAddress(&phWv1,  g_hWv1);
    cudaGetSymbolAddress(&phWv2,  g_hWv2);
    cudaGetSymbolAddress(&phMemK, g_hMemK);
    cudaGetSymbolAddress(&phMemV, g_hMemV);

    cudaFuncSetAttribute(proj_h<float>,
                         cudaFuncAttributeMaxDynamicSharedMemorySize, PROJ_SMEM);
    cudaFuncSetAttribute(proj_h<__half>,
                         cudaFuncAttributeMaxDynamicSharedMemorySize, PROJ_SMEM);
    cudaFuncSetAttribute(attn_mma,
                         cudaFuncAttributeMaxDynamicSharedMemorySize, ATTN_SMEM);

    /* side stream + events, created once outside any capture (first call is
       the correctness run). No device memory is allocated here. */
    static cudaStream_t s1 = nullptr;
    static cudaEvent_t eFork, eW, eV2, eQ, eV1;
    if (!s1) {
        cudaStreamCreateWithFlags(&s1, cudaStreamNonBlocking);
        cudaEventCreateWithFlags(&eFork, cudaEventDisableTiming);
        cudaEventCreateWithFlags(&eW,    cudaEventDisableTiming);
        cudaEventCreateWithFlags(&eV2,   cudaEventDisableTiming);
        cudaEventCreateWithFlags(&eQ,    cudaEventDisableTiming);
        cudaEventCreateWithFlags(&eV1,   cudaEventDisableTiming);
    }

    const int BIGN8 = (int)(((size_t)Bq * Mseq * Ee) / 8);

    /* fork side stream off stream 0 */
    cudaEventRecord(eFork, 0);
    cudaStreamWaitEvent(s1, eFork, 0);

    /* ---- side stream: weights, value2, q/v1, mem, small projections ---- */
    cvt_w4_kernel<<<dim3(512, 4), 256, 0, s1>>>(
        (const float4*)Wq, (const float4*)Wk, (const float4*)Wv1, (const float4*)Wv2,
        (uint4*)phWq, (uint4*)phWk, (uint4*)phWv1, (uint4*)phWv2, Ee * Ee / 8);
    cudaEventRecord(eW, s1);
    cvt_f16_kernel<<<4096, 256, 0, s1>>>((const float4*)value2,
                                         (uint4*)phV2in, BIGN8);
    cudaEventRecord(eV2, s1);
    cvt_qv_kernel<<<dim3(128, 2), 256, 0, s1>>>(
        (const float4*)query, (const float4*)value1,
        (uint4*)phQ, (uint4*)phV1, Bq * Ee / 8);
    cvt_mem_kernel<<<40, 256, 0, s1>>>(mem, (__half*)phMemK, (__half*)phMemV,
                                       MEMN * Ee);
    proj_h<float><<<dim3(8, 1), 256, PROJ_SMEM, s1>>>(
        (const __half*)phQ,  (const __half*)phWq,  bq,  gq,  sq,  (float*)pq);
    cudaEventRecord(eQ, s1);
    proj_h<float><<<dim3(8, 1), 256, PROJ_SMEM, s1>>>(
        (const __half*)phV1, (const __half*)phWv1, bv1, gv1, sv1, (float*)pv1);
    cudaEventRecord(eV1, s1);

    /* ---- main stream: key cvt, big projections, attention, finalize ---- */
    cvt_f16_kernel<<<4096, 256>>>((const float4*)key, (uint4*)phKey, BIGN8);
    cudaStreamWaitEvent(0, eW, 0);
    proj_h<__half><<<dim3(8, 1024), 256, PROJ_SMEM>>>(
        (const __half*)phKey, (const __half*)phWk, bk, gk, sk, (__half*)phKout);
    cudaStreamWaitEvent(0, eV2, 0);
    proj_h<__half><<<dim3(8, 1024), 256, PROJ_SMEM>>>(
        (const __half*)phV2in, (const __half*)phWv2, bv2, gv2, sv2,
        (__half*)phV2out);
    cudaStreamWaitEvent(0, eQ, 0);   /* g_q + hMemK ready */
    attn_mma<<<Bq * Hh, 256, ATTN_SMEM>>>(mask, Wb, bb, Wl, bl);
    cudaStreamWaitEvent(0, eV1, 0);  /* g_v1 ready */
    finalize_kernel<<<Bq * Hh, 256>>>(Wl2, bl2, out);
}